// round 2
// baseline (speedup 1.0000x reference)
#include <cuda_runtime.h>

// ---------------- scratch (no allocations allowed) ----------------
__device__ float g_xblur[8 * 256 * 128 * 128];  // blurred input, 134 MB
__device__ float g_style[8 * 256];              // style[b,i]
__device__ float g_wsq[256 * 256];              // sum_t w[o,i,t]^2
__device__ float g_partial[4096];               // per-half-plane sum of squares
__device__ float g_rscale[8 * 256];             // rsqrt(ms+eps)*g[i]*style[b,i]
__device__ float g_alpha[8 * 256];              // scale * demod[b,o]

#define LRELU_SLOPE 0.2f
#define SQRT2F 1.41421356237309515f

// ---------------- style[b,i] = s[b,:] @ style_w[i,:] + style_b[i] ----------------
// one warp per (b,i); 2048 warps
__global__ void style_kernel(const float* __restrict__ s,
                             const float* __restrict__ style_w,
                             const float* __restrict__ style_b) {
    int wg = blockIdx.x * 8 + (threadIdx.x >> 5);  // 0..2047 = b*256+i
    int lane = threadIdx.x & 31;
    int b = wg >> 8, i = wg & 255;
    const float* sp = s + b * 512;
    const float* wp = style_w + i * 512;
    float acc = 0.f;
#pragma unroll 4
    for (int j = lane; j < 512; j += 32) acc += sp[j] * wp[j];
#pragma unroll
    for (int o = 16; o; o >>= 1) acc += __shfl_xor_sync(0xffffffffu, acc, o);
    if (lane == 0) g_style[wg] = acc + style_b[i];
}

// ---------------- wsq[o,i] = sum over 9 taps of w^2 ----------------
__global__ void wsq_kernel(const float* __restrict__ w) {
    int g = blockIdx.x * 256 + threadIdx.x;  // 0..65535 = o*256+i
    const float* p = w + g * 9;
    float a = 0.f;
#pragma unroll
    for (int t = 0; t < 9; t++) { float v = p[t]; a += v * v; }
    g_wsq[g] = a;
}

// ---------------- blur (separable 5x5 binomial, zero pad 2) + sum of squares ----------------
// 2 CTAs per (b,c) plane; each handles 64 output rows + 2-row halo
__global__ void blur_kernel(const float* __restrict__ x) {
    __shared__ float hb[68][128];
    __shared__ float red[8];
    int plane = blockIdx.x >> 1;
    int h0 = (blockIdx.x & 1) * 64;
    int tid = threadIdx.x;
    const float* xp = x + (long)plane * 16384;

    // horizontal pass (reads global, L1-cached)
    for (int idx = tid; idx < 68 * 128; idx += 256) {
        int r = idx >> 7, wv = idx & 127;
        int h = h0 - 2 + r;
        float acc = 0.f;
        if ((unsigned)h < 128u) {
            const float* row = xp + h * 128;
            acc = 6.f * row[wv];
            if (wv >= 1)   acc += 4.f * row[wv - 1];
            if (wv >= 2)   acc += row[wv - 2];
            if (wv <= 126) acc += 4.f * row[wv + 1];
            if (wv <= 125) acc += row[wv + 2];
        }
        hb[r][wv] = acc;
    }
    __syncthreads();

    // vertical pass + sumsq
    float ss = 0.f;
    float* outp = g_xblur + (long)plane * 16384 + h0 * 128;
    for (int idx = tid; idx < 64 * 128; idx += 256) {
        int hl = idx >> 7, wv = idx & 127;
        int r = hl + 2;
        float v = (hb[r - 2][wv] + hb[r + 2][wv]
                   + 4.f * (hb[r - 1][wv] + hb[r + 1][wv])
                   + 6.f * hb[r][wv]) * (1.f / 256.f);
        outp[idx] = v;
        ss += v * v;
    }
#pragma unroll
    for (int o = 16; o; o >>= 1) ss += __shfl_xor_sync(0xffffffffu, ss, o);
    if ((tid & 31) == 0) red[tid >> 5] = ss;
    __syncthreads();
    if (tid == 0) {
        float t = 0.f;
#pragma unroll
        for (int k = 0; k < 8; k++) t += red[k];
        g_partial[blockIdx.x] = t;
    }
}

// ---------------- rscale[b,i] = rsqrt(ms+eps) * norm_g[i] * style[b,i] ----------------
__global__ void rscale_kernel(const float* __restrict__ norm_g) {
    int p = blockIdx.x * 256 + threadIdx.x;  // 0..2047
    int i = p & 255;
    float ss = g_partial[2 * p] + g_partial[2 * p + 1];
    float ms = ss * (1.f / 16384.f);
    g_rscale[p] = rsqrtf(ms + 1e-8f) * norm_g[i] * g_style[p];
}

// ---------------- alpha[b,o] = scale * rsqrt(scale^2 * sum_i style^2*wsq + eps) ----------------
// one warp per (b,o)
__global__ void alpha_kernel() {
    int wg = blockIdx.x * 8 + (threadIdx.x >> 5);  // b*256+o
    int lane = threadIdx.x & 31;
    int b = wg >> 8, o = wg & 255;
    const float* st = g_style + b * 256;
    const float* wq = g_wsq + o * 256;
    float acc = 0.f;
#pragma unroll 2
    for (int i = lane; i < 256; i += 32) { float sv = st[i]; acc += sv * sv * wq[i]; }
#pragma unroll
    for (int off = 16; off; off >>= 1) acc += __shfl_xor_sync(0xffffffffu, acc, off);
    if (lane == 0) {
        const float sc = 1.f / 48.f;  // 1/sqrt(256*9)
        g_alpha[wg] = sc * rsqrtf(sc * sc * acc + 1e-8f);
    }
}

// ---------------- implicit-GEMM conv, stride 2, pad 1 ----------------
// per batch:  C[o,n] = sum_k A[o,k] * B[k,n],  O=256, N=4096, K=2304
// A = conv_w reshaped [256,2304]; B = im2col(g_xblur * rscale)
// tiling: BM=BN=128, BK=8, 256 threads, 8x8 register tile (split 4+4 fragments)
__global__ __launch_bounds__(256, 2)
void conv_kernel(const float* __restrict__ w,
                 const float* __restrict__ conv_b,
                 float* __restrict__ out) {
    __shared__ float As[2][8][128];
    __shared__ float Bs[2][8][128];
    const int tid = threadIdx.x;
    const int b = blockIdx.z;
    const int mBase = blockIdx.y * 128;
    const int nBase = blockIdx.x * 128;

    const int arow = tid >> 1;           // 0..127
    const int acol = (tid & 1) << 2;     // 0 or 4
    const int krow = tid >> 5;           // 0..7
    const int ncol = (tid & 31) << 2;    // 0..124
    const int tyi = tid >> 4;            // 0..15 (m)
    const int txi = tid & 15;            // 0..15 (n)

    const float* aPtrBase = w + (long)(mBase + arow) * 2304 + acol;
    const float* xbB = g_xblur + (long)b * 256 * 16384;
    const float* rsB = g_rscale + b * 256;

    float c[8][8];
#pragma unroll
    for (int i = 0; i < 8; i++)
#pragma unroll
        for (int j = 0; j < 8; j++) c[i][j] = 0.f;

    float4 aReg;
    float bReg[4];

    // ---- prologue: fetch tile 0 ----
    aReg = *reinterpret_cast<const float4*>(aPtrBase);
    {
        int k = krow;
        int ic = k / 9; int t = k - ic * 9; int tyy = t / 3; int txx = t - tyy * 3;
        const float* xp = xbB + ic * 16384;
        float rs = rsB[ic];
#pragma unroll
        for (int j = 0; j < 4; j++) {
            int n = nBase + ncol + j;
            int oy = n >> 6, ox = n & 63;
            int iy = 2 * oy - 1 + tyy, ix = 2 * ox - 1 + txx;
            float v = 0.f;
            if ((unsigned)iy < 128u && (unsigned)ix < 128u) v = xp[iy * 128 + ix] * rs;
            bReg[j] = v;
        }
    }
    As[0][acol + 0][arow] = aReg.x;
    As[0][acol + 1][arow] = aReg.y;
    As[0][acol + 2][arow] = aReg.z;
    As[0][acol + 3][arow] = aReg.w;
    *reinterpret_cast<float4*>(&Bs[0][krow][ncol]) =
        make_float4(bReg[0], bReg[1], bReg[2], bReg[3]);
    __syncthreads();

    const int nIter = 2304 / 8;  // 288
    for (int it = 0; it < nIter; ++it) {
        int cur = it & 1;
        bool hasNext = (it + 1 < nIter);
        if (hasNext) {
            int k0 = (it + 1) * 8;
            aReg = *reinterpret_cast<const float4*>(aPtrBase + k0);
            int k = k0 + krow;
            int ic = k / 9; int t = k - ic * 9; int tyy = t / 3; int txx = t - tyy * 3;
            const float* xp = xbB + ic * 16384;
            float rs = rsB[ic];
#pragma unroll
            for (int j = 0; j < 4; j++) {
                int n = nBase + ncol + j;
                int oy = n >> 6, ox = n & 63;
                int iy = 2 * oy - 1 + tyy, ix = 2 * ox - 1 + txx;
                float v = 0.f;
                if ((unsigned)iy < 128u && (unsigned)ix < 128u) v = xp[iy * 128 + ix] * rs;
                bReg[j] = v;
            }
        }
        // ---- compute from smem[cur]: split fragments (conflict-free LDS.128) ----
#pragma unroll
        for (int kk = 0; kk < 8; kk++) {
            float a[8], bb[8];
            *reinterpret_cast<float4*>(&a[0]) =
                *reinterpret_cast<const float4*>(&As[cur][kk][tyi * 4]);
            *reinterpret_cast<float4*>(&a[4]) =
                *reinterpret_cast<const float4*>(&As[cur][kk][64 + tyi * 4]);
            *reinterpret_cast<float4*>(&bb[0]) =
                *reinterpret_cast<const float4*>(&Bs[cur][kk][txi * 4]);
            *reinterpret_cast<float4*>(&bb[4]) =
                *reinterpret_cast<const float4*>(&Bs[cur][kk][64 + txi * 4]);
#pragma unroll
            for (int i = 0; i < 8; i++)
#pragma unroll
                for (int j = 0; j < 8; j++) c[i][j] += a[i] * bb[j];
        }
        if (hasNext) {
            int nxt = cur ^ 1;
            As[nxt][acol + 0][arow] = aReg.x;
            As[nxt][acol + 1][arow] = aReg.y;
            As[nxt][acol + 2][arow] = aReg.z;
            As[nxt][acol + 3][arow] = aReg.w;
            *reinterpret_cast<float4*>(&Bs[nxt][krow][ncol]) =
                make_float4(bReg[0], bReg[1], bReg[2], bReg[3]);
        }
        __syncthreads();
    }

    // ---- epilogue: alpha, bias, scaled LeakyReLU ----
#pragma unroll
    for (int ih = 0; ih < 2; ih++) {
#pragma unroll
        for (int ii = 0; ii < 4; ii++) {
            int i = ih * 4 + ii;
            int o = mBase + ih * 64 + tyi * 4 + ii;
            float alpha = g_alpha[b * 256 + o];
            float bias = conv_b[o];
            float* op = out + (long)(b * 256 + o) * 4096 + nBase;
            float t0[4], t1[4];
#pragma unroll
            for (int jj = 0; jj < 4; jj++) {
                float v = c[i][jj] * alpha + bias;
                t0[jj] = (v >= 0.f ? v : LRELU_SLOPE * v) * SQRT2F;
                float v2 = c[i][4 + jj] * alpha + bias;
                t1[jj] = (v2 >= 0.f ? v2 : LRELU_SLOPE * v2) * SQRT2F;
            }
            *reinterpret_cast<float4*>(op + txi * 4) =
                make_float4(t0[0], t0[1], t0[2], t0[3]);
            *reinterpret_cast<float4*>(op + 64 + txi * 4) =
                make_float4(t1[0], t1[1], t1[2], t1[3]);
        }
    }
}

// ---------------- launch ----------------
extern "C" void kernel_launch(void* const* d_in, const int* in_sizes, int n_in,
                              void* d_out, int out_size) {
    const float* x       = (const float*)d_in[0];  // [8,256,128,128]
    const float* s       = (const float*)d_in[1];  // [8,512]
    const float* conv_w  = (const float*)d_in[2];  // [256,256,3,3]
    const float* conv_b  = (const float*)d_in[3];  // [256]
    const float* style_w = (const float*)d_in[4];  // [256,512]
    const float* style_b = (const float*)d_in[5];  // [256]
    const float* norm_g  = (const float*)d_in[6];  // [256]
    float* out = (float*)d_out;                    // [8,256,64,64]

    style_kernel<<<256, 256>>>(s, style_w, style_b);
    wsq_kernel<<<256, 256>>>(conv_w);
    blur_kernel<<<4096, 256>>>(x);
    rscale_kernel<<<8, 256>>>(norm_g);
    alpha_kernel<<<256, 256>>>();
    conv_kernel<<<dim3(32, 2, 8), 256>>>(conv_w, conv_b, out);
}

// round 4
// speedup vs baseline: 1.6265x; 1.6265x over previous
#include <cuda_runtime.h>
#include <cuda_bf16.h>
#include <cstdint>

// ============================ helpers ============================
__device__ __forceinline__ uint32_t smem_to_u32(const void* smem_ptr) {
    uint32_t addr;
    asm("{ .reg .u64 tmp; cvta.to.shared.u64 tmp, %1; cvt.u32.u64 %0, tmp; }"
        : "=r"(addr) : "l"(smem_ptr));
    return addr;
}

#define CP_ASYNC16(dst, src) \
    asm volatile("cp.async.cg.shared.global [%0], [%1], 16;" \
                 :: "r"(dst), "l"(src) : "memory")
#define CP_COMMIT() asm volatile("cp.async.commit_group;" ::: "memory")
#define CP_WAIT_ALL() asm volatile("cp.async.wait_group 0;" ::: "memory")

__device__ __forceinline__ void ldmat_x4(uint32_t* r, uint32_t addr) {
    asm volatile("ldmatrix.sync.aligned.m8n8.x4.shared.b16 {%0,%1,%2,%3}, [%4];"
                 : "=r"(r[0]), "=r"(r[1]), "=r"(r[2]), "=r"(r[3]) : "r"(addr));
}
__device__ __forceinline__ void ldmat_x4_t(uint32_t* r, uint32_t addr) {
    asm volatile("ldmatrix.sync.aligned.m8n8.x4.trans.shared.b16 {%0,%1,%2,%3}, [%4];"
                 : "=r"(r[0]), "=r"(r[1]), "=r"(r[2]), "=r"(r[3]) : "r"(addr));
}
__device__ __forceinline__ void mma16816(float* c, const uint32_t* a,
                                         uint32_t b0, uint32_t b1) {
    asm volatile(
        "mma.sync.aligned.m16n8k16.row.col.f32.bf16.bf16.f32 "
        "{%0,%1,%2,%3}, {%4,%5,%6,%7}, {%8,%9}, {%0,%1,%2,%3};"
        : "+f"(c[0]), "+f"(c[1]), "+f"(c[2]), "+f"(c[3])
        : "r"(a[0]), "r"(a[1]), "r"(a[2]), "r"(a[3]), "r"(b0), "r"(b1));
}

// ============================ scratch globals ============================
// parity planes, packed u32 = (bf16_hi << 16) | bf16_lo of blurred x
// layout [b][py][px][ic][65 rows][72 cols]; row 0 / col 0 are zero borders
#define PP_PLANE 4680  // 65*72
__device__ unsigned g_pp[8L * 2 * 2 * 256 * PP_PLANE];   // ~153 MB
__device__ float g_style[8 * 256];
__device__ float g_wsq[256 * 256];
__device__ float g_partial[4096];
__device__ float g_rscale[8 * 256];
__device__ float g_alpha[8 * 256];
// per-batch scaled weights, reordered k = t*256+ic, split bf16 hi/lo
__device__ __align__(256) __nv_bfloat16 g_wAb_hi[8L * 256 * 2304];
__device__ __align__(256) __nv_bfloat16 g_wAb_lo[8L * 256 * 2304];

#define LRELU_SLOPE 0.2f
#define SQRT2F 1.41421356237309515f

// ============================ small kernels ============================
__global__ void style_kernel(const float* __restrict__ s,
                             const float* __restrict__ style_w,
                             const float* __restrict__ style_b) {
    int wg = blockIdx.x * 8 + (threadIdx.x >> 5);
    int lane = threadIdx.x & 31;
    int b = wg >> 8, i = wg & 255;
    const float* sp = s + b * 512;
    const float* wp = style_w + i * 512;
    float acc = 0.f;
#pragma unroll 4
    for (int j = lane; j < 512; j += 32) acc += sp[j] * wp[j];
#pragma unroll
    for (int o = 16; o; o >>= 1) acc += __shfl_xor_sync(0xffffffffu, acc, o);
    if (lane == 0) g_style[wg] = acc + style_b[i];
}

__global__ void wsq_kernel(const float* __restrict__ w) {
    int g = blockIdx.x * 256 + threadIdx.x;
    const float* p = w + g * 9;
    float a = 0.f;
#pragma unroll
    for (int t = 0; t < 9; t++) { float v = p[t]; a += v * v; }
    g_wsq[g] = a;
}

// zero row-0 and col-0 of each parity plane
__global__ void zero_border_kernel() {
    long plane = blockIdx.x;  // 8192 planes
    unsigned* p = g_pp + plane * PP_PLANE;
    int t = threadIdx.x;      // 160 threads
    if (t < 72) p[t] = 0u;
    int r = t - 72;
    if (r >= 0 && r < 65) p[r * 72] = 0u;
}

// blur (separable 5x5 binomial, zero pad 2) + sumsq; writes packed parity planes
__global__ void blur_kernel(const float* __restrict__ x) {
    __shared__ float hb[68][128];
    __shared__ float red[8];
    int plane = blockIdx.x >> 1;
    int b = plane >> 8, c = plane & 255;
    int h0 = (blockIdx.x & 1) * 64;
    int tid = threadIdx.x;
    const float* xp = x + (long)plane * 16384;

    for (int idx = tid; idx < 68 * 128; idx += 256) {
        int r = idx >> 7, wv = idx & 127;
        int h = h0 - 2 + r;
        float acc = 0.f;
        if ((unsigned)h < 128u) {
            const float* row = xp + h * 128;
            acc = 6.f * row[wv];
            if (wv >= 1)   acc += 4.f * row[wv - 1];
            if (wv >= 2)   acc += row[wv - 2];
            if (wv <= 126) acc += 4.f * row[wv + 1];
            if (wv <= 125) acc += row[wv + 2];
        }
        hb[r][wv] = acc;
    }
    __syncthreads();

    float ss = 0.f;
    for (int idx = tid; idx < 64 * 128; idx += 256) {
        int hl = idx >> 7, wv = idx & 127;
        int r = hl + 2;
        float v = (hb[r - 2][wv] + hb[r + 2][wv]
                   + 4.f * (hb[r - 1][wv] + hb[r + 1][wv])
                   + 6.f * hb[r][wv]) * (1.f / 256.f);
        int iy = h0 + hl, ix = wv;
        __nv_bfloat16 h16 = __float2bfloat16(v);
        __nv_bfloat16 l16 = __float2bfloat16(v - __bfloat162float(h16));
        unsigned packed = ((unsigned)__bfloat16_as_ushort(h16) << 16)
                        | (unsigned)__bfloat16_as_ushort(l16);
        long dst = ((((long)(b * 2 + (iy & 1)) * 2 + (ix & 1)) * 256 + c) * 65
                    + ((iy >> 1) + 1)) * 72 + ((ix >> 1) + 1);
        g_pp[dst] = packed;
        ss += v * v;
    }
#pragma unroll
    for (int o = 16; o; o >>= 1) ss += __shfl_xor_sync(0xffffffffu, ss, o);
    if ((tid & 31) == 0) red[tid >> 5] = ss;
    __syncthreads();
    if (tid == 0) {
        float t = 0.f;
#pragma unroll
        for (int k = 0; k < 8; k++) t += red[k];
        g_partial[blockIdx.x] = t;
    }
}

__global__ void rscale_kernel(const float* __restrict__ norm_g) {
    int p = blockIdx.x * 256 + threadIdx.x;
    int i = p & 255;
    float ss = g_partial[2 * p] + g_partial[2 * p + 1];
    float ms = ss * (1.f / 16384.f);
    g_rscale[p] = rsqrtf(ms + 1e-8f) * norm_g[i] * g_style[p];
}

__global__ void alpha_kernel() {
    int wg = blockIdx.x * 8 + (threadIdx.x >> 5);
    int lane = threadIdx.x & 31;
    int b = wg >> 8, o = wg & 255;
    const float* st = g_style + b * 256;
    const float* wq = g_wsq + o * 256;
    float acc = 0.f;
#pragma unroll 2
    for (int i = lane; i < 256; i += 32) { float sv = st[i]; acc += sv * sv * wq[i]; }
#pragma unroll
    for (int off = 16; off; off >>= 1) acc += __shfl_xor_sync(0xffffffffu, acc, off);
    if (lane == 0) {
        const float sc = 1.f / 48.f;
        g_alpha[wg] = sc * rsqrtf(sc * sc * acc + 1e-8f);
    }
}

// per-batch scaled weights: A'[b,o,k=t*256+ic] = w[o,ic,t] * rscale[b,ic], split hi/lo
__global__ void wsplit_b_kernel(const float* __restrict__ w) {
    int b = blockIdx.y;
    int idx = blockIdx.x * 256 + threadIdx.x;   // 0..589823
    int o = idx / 2304;
    int k = idx - o * 2304;
    int t = k >> 8;
    int ic = k & 255;
    float v = w[(o * 256 + ic) * 9 + t] * g_rscale[b * 256 + ic];
    __nv_bfloat16 h = __float2bfloat16(v);
    long dst = (long)(b * 256 + o) * 2304 + k;
    g_wAb_hi[dst] = h;
    g_wAb_lo[dst] = __float2bfloat16(v - __bfloat162float(h));
}

// ============================ HMMA conv GEMM ============================
// per (b, mTile, nTile): C[128 o][128 n], K = 2304 = 36 chunks of 64 (k = t*256+ic)
// bf16 split: C = AhiBhi + AhiBlo + AloBhi
// smem: double-buffered A(hi/lo) 16KB each, B(hi/lo) 16KB each -> 128KB

#define SA_H(st) ((st) * 16384)
#define SA_L(st) (32768 + (st) * 16384)
#define SB_H(st) (65536 + (st) * 16384)
#define SB_L(st) (98304 + (st) * 16384)
#define CONV_SMEM 131072

__global__ __launch_bounds__(256, 1)
void mma_conv_kernel(const float* __restrict__ conv_b, float* __restrict__ out) {
    extern __shared__ __align__(1024) char smem[];
    const uint32_t sb = smem_to_u32(smem);
    const int tid = threadIdx.x;
    const int lane = tid & 31;
    const int wid = tid >> 5;
    const int warpM = wid >> 2;         // 0..1
    const int warpN = wid & 3;          // 0..3
    const int b = blockIdx.z;
    const int mBase = blockIdx.y * 128;
    const int oyBase = blockIdx.x * 2;
    const int nBase = blockIdx.x * 128;

    // ---- staging constants ----
    const int am = tid >> 1;            // A: m row 0..127
    const int ahalf = tid & 1;          // A: 4-unit half
    const long aSrcBase = (long)(b * 256 + mBase + am) * 2304 + ahalf * 32;
    const int am7 = am & 7;
    const int aDstRow = am * 128;

    const int icl = tid >> 2;           // B: k row 0..63
    const int q = tid & 3;              // B: n quarter
    const int icl7 = icl & 7;
    const int bDstRow = icl * 256;

    // ---- fragment address constants ----
    const int laneRow = lane & 15;
    const int laneSel = lane >> 4;
    const int mW = warpM * 64;
    const int nW = warpN * 32;
    int mRowB[4], mRow7[4];
#pragma unroll
    for (int mt = 0; mt < 4; mt++) {
        int m = mW + mt * 16 + laneRow;
        mRowB[mt] = m * 128;
        mRow7[mt] = m & 7;
    }
    const int bKRow = laneRow * 256;
    const int bK7 = laneRow & 7;
    int bUn[2];
#pragma unroll
    for (int nt2 = 0; nt2 < 2; nt2++)
        bUn[nt2] = (nW >> 3) + nt2 * 2 + laneSel;

    float acc[4][4][4];
#pragma unroll
    for (int i = 0; i < 4; i++)
#pragma unroll
        for (int j = 0; j < 4; j++)
#pragma unroll
            for (int k = 0; k < 4; k++) acc[i][j][k] = 0.f;

    uint32_t bq[32];

    // ===== helper lambdas =====
    auto issueA = [&](int stage, int chunk) {
        const __nv_bfloat16* sh = g_wAb_hi + aSrcBase + chunk * 64;
        const __nv_bfloat16* sl = g_wAb_lo + aSrcBase + chunk * 64;
        uint32_t dh = sb + SA_H(stage) + aDstRow;
        uint32_t dl = sb + SA_L(stage) + aDstRow;
#pragma unroll
        for (int j = 0; j < 4; j++) {
            int u = ahalf * 4 + j;
            int sw = ((u ^ am7) & 7) * 16;
            CP_ASYNC16(dh + sw, sh + j * 8);
            CP_ASYNC16(dl + sw, sl + j * 8);
        }
    };
    auto issueB = [&](int chunk) {
        int tap = chunk >> 2;
        int icq = chunk & 3;
        int ty = (tap >= 6) ? 2 : (tap >= 3 ? 1 : 0);
        int tx = tap - ty * 3;
        int py = (ty == 1) ? 0 : 1;
        int px = (tx == 1) ? 0 : 1;
        int row = oyBase + (q >> 1) + (ty != 0);
        int colBase = (q & 1) * 32 + (tx != 0);
        const unsigned* src = g_pp
            + ((long)((b * 2 + py) * 2 + px) * 256 + icq * 64 + icl) * (long)PP_PLANE
            + row * 72 + colBase;
#pragma unroll
        for (int j = 0; j < 32; j++) bq[j] = src[j];
    };
    auto storeB = [&](int stage) {
        char* bh = smem + SB_H(stage);
        char* bl = smem + SB_L(stage);
#pragma unroll
        for (int g = 0; g < 4; g++) {
            int u = q * 4 + g;
            int off = bDstRow + ((u & 8) | ((u ^ icl7) & 7)) * 16;
            uint4 vh, vl;
            vh.x = __byte_perm(bq[g * 8 + 0], bq[g * 8 + 1], 0x7632);
            vl.x = __byte_perm(bq[g * 8 + 0], bq[g * 8 + 1], 0x5410);
            vh.y = __byte_perm(bq[g * 8 + 2], bq[g * 8 + 3], 0x7632);
            vl.y = __byte_perm(bq[g * 8 + 2], bq[g * 8 + 3], 0x5410);
            vh.z = __byte_perm(bq[g * 8 + 4], bq[g * 8 + 5], 0x7632);
            vl.z = __byte_perm(bq[g * 8 + 4], bq[g * 8 + 5], 0x5410);
            vh.w = __byte_perm(bq[g * 8 + 6], bq[g * 8 + 7], 0x7632);
            vl.w = __byte_perm(bq[g * 8 + 6], bq[g * 8 + 7], 0x5410);
            *reinterpret_cast<uint4*>(bh + off) = vh;
            *reinterpret_cast<uint4*>(bl + off) = vl;
        }
    };

    // ===== prologue: stage chunk 0 =====
    issueB(0);
    issueA(0, 0);
    CP_COMMIT();
    storeB(0);
    CP_WAIT_ALL();
    __syncthreads();

    // ===== mainloop =====
    for (int chunk = 0; chunk < 36; ++chunk) {
        const int cur = chunk & 1;
        const bool hasNext = (chunk + 1 < 36);
        if (hasNext) {
            issueB(chunk + 1);          // LDGs in flight under compute
            issueA(cur ^ 1, chunk + 1);
            CP_COMMIT();
        }

        const uint32_t aH_base = sb + SA_H(cur);
        const uint32_t aL_base = sb + SA_L(cur);
        const uint32_t bH_base = sb + SB_H(cur);
        const uint32_t bL_base = sb + SB_L(cur);

#pragma unroll
        for (int kk = 0; kk < 4; kk++) {
            uint32_t aH[4][4], aL[4][4], bH[2][4], bL[2][4];
#pragma unroll
            for (int mt = 0; mt < 4; mt++) {
                int u = kk * 2 + laneSel;
                int off = mRowB[mt] + ((u ^ mRow7[mt]) & 7) * 16;
                ldmat_x4(aH[mt], aH_base + off);
                ldmat_x4(aL[mt], aL_base + off);
            }
#pragma unroll
            for (int nt2 = 0; nt2 < 2; nt2++) {
                int off = kk * 16 * 256 + bKRow
                        + ((bUn[nt2] & 8) | ((bUn[nt2] ^ bK7) & 7)) * 16;
                ldmat_x4_t(bH[nt2], bH_base + off);
                ldmat_x4_t(bL[nt2], bL_base + off);
            }
#pragma unroll
            for (int mt = 0; mt < 4; mt++) {
#pragma unroll
                for (int nt = 0; nt < 4; nt++) {
                    int nt2 = nt >> 1, sub = (nt & 1) * 2;
                    mma16816(acc[mt][nt], aH[mt], bH[nt2][sub], bH[nt2][sub + 1]);
                    mma16816(acc[mt][nt], aH[mt], bL[nt2][sub], bL[nt2][sub + 1]);
                    mma16816(acc[mt][nt], aL[mt], bH[nt2][sub], bH[nt2][sub + 1]);
                }
            }
        }

        if (hasNext) storeB(cur ^ 1);
        CP_WAIT_ALL();
        __syncthreads();
    }

    // ===== epilogue: alpha, bias, scaled LeakyReLU =====
    const int rowInTile = lane >> 2;
    const int colInTile = (lane & 3) * 2;
#pragma unroll
    for (int mt = 0; mt < 4; mt++) {
        int o0 = mBase + mW + mt * 16 + rowInTile;
        int o1 = o0 + 8;
        float al0 = g_alpha[b * 256 + o0], bi0 = conv_b[o0];
        float al1 = g_alpha[b * 256 + o1], bi1 = conv_b[o1];
        float* p0 = out + (long)(b * 256 + o0) * 4096 + nBase + nW + colInTile;
        float* p1 = out + (long)(b * 256 + o1) * 4096 + nBase + nW + colInTile;
#pragma unroll
        for (int nt = 0; nt < 4; nt++) {
            float2 v0, v1;
            float v;
            v = acc[mt][nt][0] * al0 + bi0;
            v0.x = (v >= 0.f ? v : LRELU_SLOPE * v) * SQRT2F;
            v = acc[mt][nt][1] * al0 + bi0;
            v0.y = (v >= 0.f ? v : LRELU_SLOPE * v) * SQRT2F;
            v = acc[mt][nt][2] * al1 + bi1;
            v1.x = (v >= 0.f ? v : LRELU_SLOPE * v) * SQRT2F;
            v = acc[mt][nt][3] * al1 + bi1;
            v1.y = (v >= 0.f ? v : LRELU_SLOPE * v) * SQRT2F;
            *reinterpret_cast<float2*>(p0 + nt * 8) = v0;
            *reinterpret_cast<float2*>(p1 + nt * 8) = v1;
        }
    }
}

// ============================ launch ============================
extern "C" void kernel_launch(void* const* d_in, const int* in_sizes, int n_in,
                              void* d_out, int out_size) {
    const float* x       = (const float*)d_in[0];  // [8,256,128,128]
    const float* s       = (const float*)d_in[1];  // [8,512]
    const float* conv_w  = (const float*)d_in[2];  // [256,256,3,3]
    const float* conv_b  = (const float*)d_in[3];  // [256]
    const float* style_w = (const float*)d_in[4];  // [256,512]
    const float* style_b = (const float*)d_in[5];  // [256]
    const float* norm_g  = (const float*)d_in[6];  // [256]
    float* out = (float*)d_out;                    // [8,256,64,64]

    static int attr_set = 0;
    if (!attr_set) {
        cudaFuncSetAttribute(mma_conv_kernel,
                             cudaFuncAttributeMaxDynamicSharedMemorySize, CONV_SMEM);
        attr_set = 1;
    }

    style_kernel<<<256, 256>>>(s, style_w, style_b);
    wsq_kernel<<<256, 256>>>(conv_w);
    zero_border_kernel<<<8192, 160>>>();
    blur_kernel<<<4096, 256>>>(x);
    rscale_kernel<<<8, 256>>>(norm_g);
    wsplit_b_kernel<<<dim3(2304, 8), 256>>>(conv_w);
    alpha_kernel<<<256, 256>>>();
    mma_conv_kernel<<<dim3(32, 2, 8), 256, CONV_SMEM>>>(conv_b, out);
}

// round 6
// speedup vs baseline: 1.6658x; 1.0242x over previous
#include <cuda_runtime.h>
#include <cuda_bf16.h>
#include <cstdint>

// ============================ helpers ============================
__device__ __forceinline__ uint32_t smem_to_u32(const void* smem_ptr) {
    uint32_t addr;
    asm("{ .reg .u64 tmp; cvta.to.shared.u64 tmp, %1; cvt.u32.u64 %0, tmp; }"
        : "=r"(addr) : "l"(smem_ptr));
    return addr;
}

#define CP_ASYNC16(dst, src) \
    asm volatile("cp.async.cg.shared.global [%0], [%1], 16;" \
                 :: "r"(dst), "l"(src) : "memory")
#define CP_COMMIT() asm volatile("cp.async.commit_group;" ::: "memory")
#define CP_WAIT_ALL() asm volatile("cp.async.wait_group 0;" ::: "memory")

__device__ __forceinline__ void ldmat_x4(uint32_t* r, uint32_t addr) {
    asm volatile("ldmatrix.sync.aligned.m8n8.x4.shared.b16 {%0,%1,%2,%3}, [%4];"
                 : "=r"(r[0]), "=r"(r[1]), "=r"(r[2]), "=r"(r[3]) : "r"(addr));
}
__device__ __forceinline__ void ldmat_x4_t(uint32_t* r, uint32_t addr) {
    asm volatile("ldmatrix.sync.aligned.m8n8.x4.trans.shared.b16 {%0,%1,%2,%3}, [%4];"
                 : "=r"(r[0]), "=r"(r[1]), "=r"(r[2]), "=r"(r[3]) : "r"(addr));
}
__device__ __forceinline__ void mma16816(float* c, const uint32_t* a,
                                         uint32_t b0, uint32_t b1) {
    asm volatile(
        "mma.sync.aligned.m16n8k16.row.col.f32.bf16.bf16.f32 "
        "{%0,%1,%2,%3}, {%4,%5,%6,%7}, {%8,%9}, {%0,%1,%2,%3};"
        : "+f"(c[0]), "+f"(c[1]), "+f"(c[2]), "+f"(c[3])
        : "r"(a[0]), "r"(a[1]), "r"(a[2]), "r"(a[3]), "r"(b0), "r"(b1));
}

// ============================ scratch globals ============================
// parity planes, packed u32 = (bf16_hi << 16) | bf16_lo of blurred x
// layout [b][py][px][ic][65 rows][72 cols]; row 0 / col 0 are zero borders
#define PP_PLANE 4680  // 65*72
__device__ unsigned g_pp[8L * 2 * 2 * 256 * PP_PLANE];   // ~153 MB
__device__ float g_style[8 * 256];
__device__ float g_partial[4096];
__device__ float g_alpha[8 * 256];
// per-batch scaled weights, reordered k = t*256+ic, split bf16 hi/lo
__device__ __align__(256) __nv_bfloat16 g_wAb_hi[8L * 256 * 2304];
__device__ __align__(256) __nv_bfloat16 g_wAb_lo[8L * 256 * 2304];

#define LRELU_SLOPE 0.2f
#define SQRT2F 1.41421356237309515f

// ============================ K1: style ============================
// style[b,i] = s[b,:] @ style_w[i,:] + style_b[i];  one warp per (b,i)
__global__ void style_kernel(const float* __restrict__ s,
                             const float* __restrict__ style_w,
                             const float* __restrict__ style_b) {
    int wg = blockIdx.x * 8 + (threadIdx.x >> 5);
    int lane = threadIdx.x & 31;
    int b = wg >> 8, i = wg & 255;
    const float* sp = s + b * 512;
    const float* wp = style_w + i * 512;
    float acc = 0.f;
#pragma unroll 4
    for (int j = lane; j < 512; j += 32) acc += sp[j] * wp[j];
#pragma unroll
    for (int o = 16; o; o >>= 1) acc += __shfl_xor_sync(0xffffffffu, acc, o);
    if (lane == 0) g_style[wg] = acc + style_b[i];
}

// ============================ K2: blur + borders ============================
// blocks [0,4096): separable 5x5 binomial blur (zero pad 2) of one half-plane,
//   packed bf16 hi/lo write into parity planes, + sum-of-squares partial.
// blocks [4096,4224): zero parity-plane borders (row 0, col 0).
#define BLUR_IN_W 136
#define BLUR_SMEM ((68 * BLUR_IN_W + 68 * 128 + 8) * 4)

__global__ __launch_bounds__(256) void blur_kernel(const float* __restrict__ x) {
    if (blockIdx.x >= 4096) {
        // border zeroing: 8192 planes x 144 slots
        int base = (blockIdx.x - 4096) * 256 + threadIdx.x;  // 32768 threads
        for (long idx = base; idx < 8192L * 144; idx += 32768) {
            long plane = idx / 144;
            int e = (int)(idx - plane * 144);
            unsigned* p = g_pp + plane * PP_PLANE;
            if (e < 72) p[e] = 0u;
            else if (e < 137) p[(e - 72) * 72] = 0u;
        }
        return;
    }

    extern __shared__ __align__(16) float sm[];
    float* in = sm;                     // [68][136], data at cols 4..131
    float* hb = sm + 68 * BLUR_IN_W;    // [68][128]
    float* red = hb + 68 * 128;

    const int plane = blockIdx.x >> 1;
    const int b = plane >> 8, c = plane & 255;
    const int h0 = (blockIdx.x & 1) * 64;
    const int tid = threadIdx.x;
    const float* xp = x + (long)plane * 16384;

    // zero padding columns (68 rows x 8 pad slots = 544 > blockDim: stride loop!)
    for (int t = tid; t < 544; t += 256) {
        int r = t >> 3, j = t & 7;
        in[r * BLUR_IN_W + (j < 4 ? j : 128 + j)] = 0.f;
    }
    // load 68 rows x 128 cols (f4), rows h0-2 .. h0+65
    for (int pos = tid; pos < 68 * 32; pos += 256) {
        int r = pos >> 5, c4 = pos & 31;
        int h = h0 - 2 + r;
        float4 v = make_float4(0.f, 0.f, 0.f, 0.f);
        if ((unsigned)h < 128u)
            v = *reinterpret_cast<const float4*>(xp + h * 128 + c4 * 4);
        *reinterpret_cast<float4*>(in + r * BLUR_IN_W + 4 + c4 * 4) = v;
    }
    __syncthreads();

    // horizontal pass: hb[r][c] = (1,4,6,4,1) dot in[r][c+2..c+6]
    for (int pos = tid; pos < 68 * 32; pos += 256) {
        int r = pos >> 5, c4 = pos & 31;
        const float* row = in + r * BLUR_IN_W + c4 * 4;
        float4 a = *reinterpret_cast<const float4*>(row);
        float4 bb = *reinterpret_cast<const float4*>(row + 4);
        float4 cc = *reinterpret_cast<const float4*>(row + 8);
        float4 o;
        o.x = a.z + 4.f * a.w + 6.f * bb.x + 4.f * bb.y + bb.z;
        o.y = a.w + 4.f * bb.x + 6.f * bb.y + 4.f * bb.z + bb.w;
        o.z = bb.x + 4.f * bb.y + 6.f * bb.z + 4.f * bb.w + cc.x;
        o.w = bb.y + 4.f * bb.z + 6.f * bb.w + 4.f * cc.x + cc.y;
        *reinterpret_cast<float4*>(hb + r * 128 + c4 * 4) = o;
    }
    __syncthreads();

    // vertical pass + pack + write + sumsq
    float ss = 0.f;
    for (int pos = tid; pos < 64 * 32; pos += 256) {
        int r = pos >> 5, c4 = pos & 31;
        const float* col = hb + r * 128 + c4 * 4;
        float4 h0v = *reinterpret_cast<const float4*>(col);
        float4 h1v = *reinterpret_cast<const float4*>(col + 128);
        float4 h2v = *reinterpret_cast<const float4*>(col + 256);
        float4 h3v = *reinterpret_cast<const float4*>(col + 384);
        float4 h4v = *reinterpret_cast<const float4*>(col + 512);
        float v0 = (h0v.x + 4.f * h1v.x + 6.f * h2v.x + 4.f * h3v.x + h4v.x) * (1.f / 256.f);
        float v1 = (h0v.y + 4.f * h1v.y + 6.f * h2v.y + 4.f * h3v.y + h4v.y) * (1.f / 256.f);
        float v2 = (h0v.z + 4.f * h1v.z + 6.f * h2v.z + 4.f * h3v.z + h4v.z) * (1.f / 256.f);
        float v3 = (h0v.w + 4.f * h1v.w + 6.f * h2v.w + 4.f * h3v.w + h4v.w) * (1.f / 256.f);
        ss += v0 * v0 + v1 * v1 + v2 * v2 + v3 * v3;

        auto pack = [](float v) -> unsigned {
            __nv_bfloat16 h16 = __float2bfloat16(v);
            __nv_bfloat16 l16 = __float2bfloat16(v - __bfloat162float(h16));
            return ((unsigned)__bfloat16_as_ushort(h16) << 16)
                 | (unsigned)__bfloat16_as_ushort(l16);
        };
        unsigned p0 = pack(v0), p1 = pack(v1), p2 = pack(v2), p3 = pack(v3);

        int iy = h0 + r;
        int py = iy & 1;
        int prow = (iy >> 1) + 1;
        int col0 = 2 * c4 + 1;
        unsigned* d0 = g_pp + ((long)((b * 2 + py) * 2 + 0) * 256 + c) * PP_PLANE
                      + prow * 72 + col0;
        unsigned* d1 = g_pp + ((long)((b * 2 + py) * 2 + 1) * 256 + c) * PP_PLANE
                      + prow * 72 + col0;
        d0[0] = p0; d0[1] = p2;
        d1[0] = p1; d1[1] = p3;
    }
#pragma unroll
    for (int o = 16; o; o >>= 1) ss += __shfl_xor_sync(0xffffffffu, ss, o);
    if ((tid & 31) == 0) red[tid >> 5] = ss;
    __syncthreads();
    if (tid == 0) {
        float t = 0.f;
#pragma unroll
        for (int k = 0; k < 8; k++) t += red[k];
        g_partial[blockIdx.x] = t;
    }
}

// ============================ K3: wsplit + rscale + alpha ============================
// one block per (o, b): stage w[o] (2304 floats) in smem; compute rscale[b,ic]
// inline; write per-batch scaled weights split to bf16 hi/lo with k = t*256+ic;
// also compute alpha[b,o] = sc*rsqrt(sc^2 * sum_ic style^2 * wsq[o,ic] + eps).
__global__ __launch_bounds__(256) void wsplit_kernel(const float* __restrict__ w,
                                                     const float* __restrict__ norm_g) {
    __shared__ float ws[2304];
    __shared__ float rs[256];
    __shared__ float red[8];
    const int o = blockIdx.x;
    const int b = blockIdx.y;
    const int tid = threadIdx.x;

    // stage w[o] coalesced
    const float4* wsrc = reinterpret_cast<const float4*>(w + (long)o * 2304);
    for (int i = tid; i < 576; i += 256)
        *reinterpret_cast<float4*>(ws + i * 4) = wsrc[i];

    // rscale[b, ic=tid]
    {
        int p = b * 256 + tid;
        float ssum = g_partial[2 * p] + g_partial[2 * p + 1];
        float ms = ssum * (1.f / 16384.f);
        rs[tid] = rsqrtf(ms + 1e-8f) * norm_g[tid] * g_style[p];
    }
    __syncthreads();

    // alpha partial: style^2 * sum_t w^2
    {
        float sv = g_style[b * 256 + tid];
        float wq = 0.f;
#pragma unroll
        for (int t = 0; t < 9; t++) { float v = ws[tid * 9 + t]; wq += v * v; }
        float pa = sv * sv * wq;
#pragma unroll
        for (int off = 16; off; off >>= 1) pa += __shfl_xor_sync(0xffffffffu, pa, off);
        if ((tid & 31) == 0) red[tid >> 5] = pa;
    }

    // split writes: dst k = t*256 + ic, coalesced in ic=tid
    {
        const float rsc = rs[tid];
        long dstBase = (long)(b * 256 + o) * 2304 + tid;
#pragma unroll
        for (int t = 0; t < 9; t++) {
            float v = ws[tid * 9 + t] * rsc;
            __nv_bfloat16 h = __float2bfloat16(v);
            g_wAb_hi[dstBase + t * 256] = h;
            g_wAb_lo[dstBase + t * 256] = __float2bfloat16(v - __bfloat162float(h));
        }
    }

    __syncthreads();
    if (tid == 0) {
        float acc = 0.f;
#pragma unroll
        for (int k = 0; k < 8; k++) acc += red[k];
        const float sc = 1.f / 48.f;  // 1/sqrt(256*9)
        g_alpha[b * 256 + o] = sc * rsqrtf(sc * sc * acc + 1e-8f);
    }
}

// ============================ K4: HMMA conv GEMM ============================
// per (b, mTile, nTile): C[128 o][128 n], K = 2304 = 36 chunks of 64 (k = t*256+ic)
// bf16 split: C = AhiBhi + AhiBlo + AloBhi
// smem: double-buffered A(hi/lo) 16KB each, B(hi/lo) 16KB each -> 128KB

#define SA_H(st) ((st) * 16384)
#define SA_L(st) (32768 + (st) * 16384)
#define SB_H(st) (65536 + (st) * 16384)
#define SB_L(st) (98304 + (st) * 16384)
#define CONV_SMEM 131072

__global__ __launch_bounds__(256, 1)
void mma_conv_kernel(const float* __restrict__ conv_b, float* __restrict__ out) {
    extern __shared__ __align__(1024) char smem[];
    const uint32_t sb = smem_to_u32(smem);
    const int tid = threadIdx.x;
    const int lane = tid & 31;
    const int wid = tid >> 5;
    const int warpM = wid >> 2;         // 0..1
    const int warpN = wid & 3;          // 0..3
    const int b = blockIdx.z;
    const int mBase = blockIdx.y * 128;
    const int oyBase = blockIdx.x * 2;
    const int nBase = blockIdx.x * 128;

    // ---- staging constants ----
    const int am = tid >> 1;            // A: m row 0..127
    const int ahalf = tid & 1;          // A: 4-unit half
    const long aSrcBase = (long)(b * 256 + mBase + am) * 2304 + ahalf * 32;
    const int am7 = am & 7;
    const int aDstRow = am * 128;

    const int icl = tid >> 2;           // B: k row 0..63
    const int q = tid & 3;              // B: n quarter
    const int icl7 = icl & 7;
    const int bDstRow = icl * 256;

    // ---- fragment address constants ----
    const int laneRow = lane & 15;
    const int laneSel = lane >> 4;
    const int mW = warpM * 64;
    const int nW = warpN * 32;
    int mRowB[4], mRow7[4];
#pragma unroll
    for (int mt = 0; mt < 4; mt++) {
        int m = mW + mt * 16 + laneRow;
        mRowB[mt] = m * 128;
        mRow7[mt] = m & 7;
    }
    const int bKRow = laneRow * 256;
    const int bK7 = laneRow & 7;
    int bUn[2];
#pragma unroll
    for (int nt2 = 0; nt2 < 2; nt2++)
        bUn[nt2] = (nW >> 3) + nt2 * 2 + laneSel;

    float acc[4][4][4];
#pragma unroll
    for (int i = 0; i < 4; i++)
#pragma unroll
        for (int j = 0; j < 4; j++)
#pragma unroll
            for (int k = 0; k < 4; k++) acc[i][j][k] = 0.f;

    uint32_t bq[32];

    // ===== helper lambdas =====
    auto issueA = [&](int stage, int chunk) {
        const __nv_bfloat16* sh = g_wAb_hi + aSrcBase + chunk * 64;
        const __nv_bfloat16* sl = g_wAb_lo + aSrcBase + chunk * 64;
        uint32_t dh = sb + SA_H(stage) + aDstRow;
        uint32_t dl = sb + SA_L(stage) + aDstRow;
#pragma unroll
        for (int j = 0; j < 4; j++) {
            int u = ahalf * 4 + j;
            int sw = ((u ^ am7) & 7) * 16;
            CP_ASYNC16(dh + sw, sh + j * 8);
            CP_ASYNC16(dl + sw, sl + j * 8);
        }
    };
    auto issueB = [&](int chunk) {
        int tap = chunk >> 2;
        int icq = chunk & 3;
        int ty = (tap >= 6) ? 2 : (tap >= 3 ? 1 : 0);
        int tx = tap - ty * 3;
        int py = (ty == 1) ? 0 : 1;
        int px = (tx == 1) ? 0 : 1;
        int row = oyBase + (q >> 1) + (ty != 0);
        int colBase = (q & 1) * 32 + (tx != 0);
        const unsigned* src = g_pp
            + ((long)((b * 2 + py) * 2 + px) * 256 + icq * 64 + icl) * (long)PP_PLANE
            + row * 72 + colBase;
#pragma unroll
        for (int j = 0; j < 32; j++) bq[j] = src[j];
    };
    auto storeB_g = [&](int stage, int g) {
        char* bh = smem + SB_H(stage);
        char* bl = smem + SB_L(stage);
        int u = q * 4 + g;
        int off = bDstRow + ((u & 8) | ((u ^ icl7) & 7)) * 16;
        uint4 vh, vl;
        vh.x = __byte_perm(bq[g * 8 + 0], bq[g * 8 + 1], 0x7632);
        vl.x = __byte_perm(bq[g * 8 + 0], bq[g * 8 + 1], 0x5410);
        vh.y = __byte_perm(bq[g * 8 + 2], bq[g * 8 + 3], 0x7632);
        vl.y = __byte_perm(bq[g * 8 + 2], bq[g * 8 + 3], 0x5410);
        vh.z = __byte_perm(bq[g * 8 + 4], bq[g * 8 + 5], 0x7632);
        vl.z = __byte_perm(bq[g * 8 + 4], bq[g * 8 + 5], 0x5410);
        vh.w = __byte_perm(bq[g * 8 + 6], bq[g * 8 + 7], 0x7632);
        vl.w = __byte_perm(bq[g * 8 + 6], bq[g * 8 + 7], 0x5410);
        *reinterpret_cast<uint4*>(bh + off) = vh;
        *reinterpret_cast<uint4*>(bl + off) = vl;
    };

    // ===== prologue: stage chunk 0 =====
    issueB(0);
    issueA(0, 0);
    CP_COMMIT();
#pragma unroll
    for (int g = 0; g < 4; g++) storeB_g(0, g);
    CP_WAIT_ALL();
    __syncthreads();

    // ===== mainloop =====
    for (int chunk = 0; chunk < 36; ++chunk) {
        const int cur = chunk & 1;
        const bool hasNext = (chunk + 1 < 36);
        if (hasNext) {
            issueB(chunk + 1);          // LDGs in flight under compute
            issueA(cur ^ 1, chunk + 1);
            CP_COMMIT();
        }

        const uint32_t aH_base = sb + SA_H(cur);
        const uint32_t aL_base = sb + SA_L(cur);
        const uint32_t bH_base = sb + SB_H(cur);
        const uint32_t bL_base = sb + SB_L(cur);

#pragma unroll
        for (int kk = 0; kk < 4; kk++) {
            uint32_t aH[4][4], aL[4][4], bH[2][4], bL[2][4];
#pragma unroll
            for (int mt = 0; mt < 4; mt++) {
                int u = kk * 2 + laneSel;
                int off = mRowB[mt] + ((u ^ mRow7[mt]) & 7) * 16;
                ldmat_x4(aH[mt], aH_base + off);
                ldmat_x4(aL[mt], aL_base + off);
            }
#pragma unroll
            for (int nt2 = 0; nt2 < 2; nt2++) {
                int off = kk * 16 * 256 + bKRow
                        + ((bUn[nt2] & 8) | ((bUn[nt2] ^ bK7) & 7)) * 16;
                ldmat_x4_t(bH[nt2], bH_base + off);
                ldmat_x4_t(bL[nt2], bL_base + off);
            }
#pragma unroll
            for (int mt = 0; mt < 4; mt++) {
#pragma unroll
                for (int nt = 0; nt < 4; nt++) {
                    int nt2 = nt >> 1, sub = (nt & 1) * 2;
                    mma16816(acc[mt][nt], aH[mt], bH[nt2][sub], bH[nt2][sub + 1]);
                    mma16816(acc[mt][nt], aH[mt], bL[nt2][sub], bL[nt2][sub + 1]);
                    mma16816(acc[mt][nt], aL[mt], bH[nt2][sub], bH[nt2][sub + 1]);
                }
            }
            // hide next-stage STS under the HMMA stream
            if (hasNext) storeB_g(cur ^ 1, kk);
        }

        CP_WAIT_ALL();
        __syncthreads();
    }

    // ===== epilogue: alpha, bias, scaled LeakyReLU =====
    const int rowInTile = lane >> 2;
    const int colInTile = (lane & 3) * 2;
#pragma unroll
    for (int mt = 0; mt < 4; mt++) {
        int o0 = mBase + mW + mt * 16 + rowInTile;
        int o1 = o0 + 8;
        float al0 = g_alpha[b * 256 + o0], bi0 = conv_b[o0];
        float al1 = g_alpha[b * 256 + o1], bi1 = conv_b[o1];
        float* p0 = out + (long)(b * 256 + o0) * 4096 + nBase + nW + colInTile;
        float* p1 = out + (long)(b * 256 + o1) * 4096 + nBase + nW + colInTile;
#pragma unroll
        for (int nt = 0; nt < 4; nt++) {
            float2 v0, v1;
            float v;
            v = acc[mt][nt][0] * al0 + bi0;
            v0.x = (v >= 0.f ? v : LRELU_SLOPE * v) * SQRT2F;
            v = acc[mt][nt][1] * al0 + bi0;
            v0.y = (v >= 0.f ? v : LRELU_SLOPE * v) * SQRT2F;
            v = acc[mt][nt][2] * al1 + bi1;
            v1.x = (v >= 0.f ? v : LRELU_SLOPE * v) * SQRT2F;
            v = acc[mt][nt][3] * al1 + bi1;
            v1.y = (v >= 0.f ? v : LRELU_SLOPE * v) * SQRT2F;
            *reinterpret_cast<float2*>(p0 + nt * 8) = v0;
            *reinterpret_cast<float2*>(p1 + nt * 8) = v1;
        }
    }
}

// ============================ launch ============================
extern "C" void kernel_launch(void* const* d_in, const int* in_sizes, int n_in,
                              void* d_out, int out_size) {
    const float* x       = (const float*)d_in[0];  // [8,256,128,128]
    const float* s       = (const float*)d_in[1];  // [8,512]
    const float* conv_w  = (const float*)d_in[2];  // [256,256,3,3]
    const float* conv_b  = (const float*)d_in[3];  // [256]
    const float* style_w = (const float*)d_in[4];  // [256,512]
    const float* style_b = (const float*)d_in[5];  // [256]
    const float* norm_g  = (const float*)d_in[6];  // [256]
    float* out = (float*)d_out;                    // [8,256,64,64]

    static int attr_set = 0;
    if (!attr_set) {
        cudaFuncSetAttribute(mma_conv_kernel,
                             cudaFuncAttributeMaxDynamicSharedMemorySize, CONV_SMEM);
        cudaFuncSetAttribute(blur_kernel,
                             cudaFuncAttributeMaxDynamicSharedMemorySize, BLUR_SMEM);
        attr_set = 1;
    }

    style_kernel<<<256, 256>>>(s, style_w, style_b);                    // launch 1
    blur_kernel<<<4224, 256, BLUR_SMEM>>>(x);                          // launch 2
    wsplit_kernel<<<dim3(256, 8), 256>>>(conv_w, norm_g);              // launch 3
    mma_conv_kernel<<<dim3(32, 2, 8), 256, CONV_SMEM>>>(conv_b, out);  // launch 4
}

// round 7
// speedup vs baseline: 2.0252x; 1.2158x over previous
#include <cuda_runtime.h>
#include <cuda_bf16.h>
#include <cstdint>

// ============================ helpers ============================
__device__ __forceinline__ uint32_t smem_to_u32(const void* smem_ptr) {
    uint32_t addr;
    asm("{ .reg .u64 tmp; cvta.to.shared.u64 tmp, %1; cvt.u32.u64 %0, tmp; }"
        : "=r"(addr) : "l"(smem_ptr));
    return addr;
}

#define CP_ASYNC16(dst, src) \
    asm volatile("cp.async.cg.shared.global [%0], [%1], 16;" \
                 :: "r"(dst), "l"(src) : "memory")
#define CP_COMMIT() asm volatile("cp.async.commit_group;" ::: "memory")
#define CP_WAIT_ALL() asm volatile("cp.async.wait_group 0;" ::: "memory")

__device__ __forceinline__ void ldmat_x4(uint32_t* r, uint32_t addr) {
    asm volatile("ldmatrix.sync.aligned.m8n8.x4.shared.b16 {%0,%1,%2,%3}, [%4];"
                 : "=r"(r[0]), "=r"(r[1]), "=r"(r[2]), "=r"(r[3]) : "r"(addr));
}
__device__ __forceinline__ void ldmat_x4_t(uint32_t* r, uint32_t addr) {
    asm volatile("ldmatrix.sync.aligned.m8n8.x4.trans.shared.b16 {%0,%1,%2,%3}, [%4];"
                 : "=r"(r[0]), "=r"(r[1]), "=r"(r[2]), "=r"(r[3]) : "r"(addr));
}
__device__ __forceinline__ void mma16816(float* c, const uint32_t* a,
                                         uint32_t b0, uint32_t b1) {
    asm volatile(
        "mma.sync.aligned.m16n8k16.row.col.f32.bf16.bf16.f32 "
        "{%0,%1,%2,%3}, {%4,%5,%6,%7}, {%8,%9}, {%0,%1,%2,%3};"
        : "+f"(c[0]), "+f"(c[1]), "+f"(c[2]), "+f"(c[3])
        : "r"(a[0]), "r"(a[1]), "r"(a[2]), "r"(a[3]), "r"(b0), "r"(b1));
}

// ============================ scratch globals ============================
// parity planes, packed u32 = (bf16_hi << 16) | bf16_lo of blurred x
// layout [b][py][px][ic][65 rows][72 cols]; row 0 / col 0 are zero borders
#define PP_PLANE 4680  // 65*72
__device__ unsigned g_pp[8L * 2 * 2 * 256 * PP_PLANE];   // ~153 MB
__device__ float g_style[8 * 256];
__device__ float g_partial[4096];
__device__ float g_alpha[8 * 256];
// per-batch scaled weights, reordered k = t*256+ic, split bf16 hi/lo
__device__ __align__(256) __nv_bfloat16 g_wAb_hi[8L * 256 * 2304];
__device__ __align__(256) __nv_bfloat16 g_wAb_lo[8L * 256 * 2304];

#define LRELU_SLOPE 0.2f
#define SQRT2F 1.41421356237309515f

// ============================ K1: style ============================
__global__ void style_kernel(const float* __restrict__ s,
                             const float* __restrict__ style_w,
                             const float* __restrict__ style_b) {
    int wg = blockIdx.x * 8 + (threadIdx.x >> 5);
    int lane = threadIdx.x & 31;
    int b = wg >> 8, i = wg & 255;
    const float* sp = s + b * 512;
    const float* wp = style_w + i * 512;
    float acc = 0.f;
#pragma unroll 4
    for (int j = lane; j < 512; j += 32) acc += sp[j] * wp[j];
#pragma unroll
    for (int o = 16; o; o >>= 1) acc += __shfl_xor_sync(0xffffffffu, acc, o);
    if (lane == 0) g_style[wg] = acc + style_b[i];
}

// ============================ K2: blur + borders ============================
#define BLUR_IN_W 136
#define BLUR_SMEM ((68 * BLUR_IN_W + 68 * 128 + 8) * 4)

__global__ __launch_bounds__(256) void blur_kernel(const float* __restrict__ x) {
    if (blockIdx.x >= 4096) {
        int base = (blockIdx.x - 4096) * 256 + threadIdx.x;
        for (long idx = base; idx < 8192L * 144; idx += 32768) {
            long plane = idx / 144;
            int e = (int)(idx - plane * 144);
            unsigned* p = g_pp + plane * PP_PLANE;
            if (e < 72) p[e] = 0u;
            else if (e < 137) p[(e - 72) * 72] = 0u;
        }
        return;
    }

    extern __shared__ __align__(16) float sm[];
    float* in = sm;                     // [68][136], data at cols 4..131
    float* hb = sm + 68 * BLUR_IN_W;    // [68][128]
    float* red = hb + 68 * 128;

    const int plane = blockIdx.x >> 1;
    const int b = plane >> 8, c = plane & 255;
    const int h0 = (blockIdx.x & 1) * 64;
    const int tid = threadIdx.x;
    const float* xp = x + (long)plane * 16384;

    for (int t = tid; t < 544; t += 256) {
        int r = t >> 3, j = t & 7;
        in[r * BLUR_IN_W + (j < 4 ? j : 128 + j)] = 0.f;
    }
    for (int pos = tid; pos < 68 * 32; pos += 256) {
        int r = pos >> 5, c4 = pos & 31;
        int h = h0 - 2 + r;
        float4 v = make_float4(0.f, 0.f, 0.f, 0.f);
        if ((unsigned)h < 128u)
            v = *reinterpret_cast<const float4*>(xp + h * 128 + c4 * 4);
        *reinterpret_cast<float4*>(in + r * BLUR_IN_W + 4 + c4 * 4) = v;
    }
    __syncthreads();

    for (int pos = tid; pos < 68 * 32; pos += 256) {
        int r = pos >> 5, c4 = pos & 31;
        const float* row = in + r * BLUR_IN_W + c4 * 4;
        float4 a = *reinterpret_cast<const float4*>(row);
        float4 bb = *reinterpret_cast<const float4*>(row + 4);
        float4 cc = *reinterpret_cast<const float4*>(row + 8);
        float4 o;
        o.x = a.z + 4.f * a.w + 6.f * bb.x + 4.f * bb.y + bb.z;
        o.y = a.w + 4.f * bb.x + 6.f * bb.y + 4.f * bb.z + bb.w;
        o.z = bb.x + 4.f * bb.y + 6.f * bb.z + 4.f * bb.w + cc.x;
        o.w = bb.y + 4.f * bb.z + 6.f * bb.w + 4.f * cc.x + cc.y;
        *reinterpret_cast<float4*>(hb + r * 128 + c4 * 4) = o;
    }
    __syncthreads();

    float ss = 0.f;
    for (int pos = tid; pos < 64 * 32; pos += 256) {
        int r = pos >> 5, c4 = pos & 31;
        const float* col = hb + r * 128 + c4 * 4;
        float4 h0v = *reinterpret_cast<const float4*>(col);
        float4 h1v = *reinterpret_cast<const float4*>(col + 128);
        float4 h2v = *reinterpret_cast<const float4*>(col + 256);
        float4 h3v = *reinterpret_cast<const float4*>(col + 384);
        float4 h4v = *reinterpret_cast<const float4*>(col + 512);
        float v0 = (h0v.x + 4.f * h1v.x + 6.f * h2v.x + 4.f * h3v.x + h4v.x) * (1.f / 256.f);
        float v1 = (h0v.y + 4.f * h1v.y + 6.f * h2v.y + 4.f * h3v.y + h4v.y) * (1.f / 256.f);
        float v2 = (h0v.z + 4.f * h1v.z + 6.f * h2v.z + 4.f * h3v.z + h4v.z) * (1.f / 256.f);
        float v3 = (h0v.w + 4.f * h1v.w + 6.f * h2v.w + 4.f * h3v.w + h4v.w) * (1.f / 256.f);
        ss += v0 * v0 + v1 * v1 + v2 * v2 + v3 * v3;

        auto pack = [](float v) -> unsigned {
            __nv_bfloat16 h16 = __float2bfloat16(v);
            __nv_bfloat16 l16 = __float2bfloat16(v - __bfloat162float(h16));
            return ((unsigned)__bfloat16_as_ushort(h16) << 16)
                 | (unsigned)__bfloat16_as_ushort(l16);
        };
        unsigned p0 = pack(v0), p1 = pack(v1), p2 = pack(v2), p3 = pack(v3);

        int iy = h0 + r;
        int py = iy & 1;
        int prow = (iy >> 1) + 1;
        int col0 = 2 * c4 + 1;
        unsigned* d0 = g_pp + ((long)((b * 2 + py) * 2 + 0) * 256 + c) * PP_PLANE
                      + prow * 72 + col0;
        unsigned* d1 = g_pp + ((long)((b * 2 + py) * 2 + 1) * 256 + c) * PP_PLANE
                      + prow * 72 + col0;
        d0[0] = p0; d0[1] = p2;
        d1[0] = p1; d1[1] = p3;
    }
#pragma unroll
    for (int o = 16; o; o >>= 1) ss += __shfl_xor_sync(0xffffffffu, ss, o);
    if ((tid & 31) == 0) red[tid >> 5] = ss;
    __syncthreads();
    if (tid == 0) {
        float t = 0.f;
#pragma unroll
        for (int k = 0; k < 8; k++) t += red[k];
        g_partial[blockIdx.x] = t;
    }
}

// ============================ K3: wsplit + rscale + alpha ============================
__global__ __launch_bounds__(256) void wsplit_kernel(const float* __restrict__ w,
                                                     const float* __restrict__ norm_g) {
    __shared__ float ws[2304];
    __shared__ float rs[256];
    __shared__ float red[8];
    const int o = blockIdx.x;
    const int b = blockIdx.y;
    const int tid = threadIdx.x;

    const float4* wsrc = reinterpret_cast<const float4*>(w + (long)o * 2304);
    for (int i = tid; i < 576; i += 256)
        *reinterpret_cast<float4*>(ws + i * 4) = wsrc[i];

    {
        int p = b * 256 + tid;
        float ssum = g_partial[2 * p] + g_partial[2 * p + 1];
        float ms = ssum * (1.f / 16384.f);
        rs[tid] = rsqrtf(ms + 1e-8f) * norm_g[tid] * g_style[p];
    }
    __syncthreads();

    {
        float sv = g_style[b * 256 + tid];
        float wq = 0.f;
#pragma unroll
        for (int t = 0; t < 9; t++) { float v = ws[tid * 9 + t]; wq += v * v; }
        float pa = sv * sv * wq;
#pragma unroll
        for (int off = 16; off; off >>= 1) pa += __shfl_xor_sync(0xffffffffu, pa, off);
        if ((tid & 31) == 0) red[tid >> 5] = pa;
    }

    {
        const float rsc = rs[tid];
        long dstBase = (long)(b * 256 + o) * 2304 + tid;
#pragma unroll
        for (int t = 0; t < 9; t++) {
            float v = ws[tid * 9 + t] * rsc;
            __nv_bfloat16 h = __float2bfloat16(v);
            g_wAb_hi[dstBase + t * 256] = h;
            g_wAb_lo[dstBase + t * 256] = __float2bfloat16(v - __bfloat162float(h));
        }
    }

    __syncthreads();
    if (tid == 0) {
        float acc = 0.f;
#pragma unroll
        for (int k = 0; k < 8; k++) acc += red[k];
        const float sc = 1.f / 48.f;  // 1/sqrt(256*9)
        g_alpha[b * 256 + o] = sc * rsqrtf(sc * sc * acc + 1e-8f);
    }
}

// ============================ K4: HMMA conv GEMM ============================
// CTA tile: M=128 (o), N=64 (one output row, ox 0..63). grid (64,2,8).
// K = 2304 = 36 chunks of 64 (k = t*256+ic).  bf16 split: C = AhiBhi+AhiBlo+AloBhi
// smem/stage: A hi/lo 16KB+16KB, B hi/lo 8KB+8KB; double-buffered = 96KB
// -> 2 CTAs/SM (launch_bounds(256,2), ~110 regs)

#define SA_H(st) ((st) * 16384)
#define SA_L(st) (32768 + (st) * 16384)
#define SB_H(st) (65536 + (st) * 8192)
#define SB_L(st) (81920 + (st) * 8192)
#define CONV_SMEM 98304

__global__ __launch_bounds__(256, 2)
void mma_conv_kernel(const float* __restrict__ conv_b, float* __restrict__ out) {
    extern __shared__ __align__(1024) char smem[];
    const uint32_t sb = smem_to_u32(smem);
    const int tid = threadIdx.x;
    const int lane = tid & 31;
    const int wid = tid >> 5;
    const int warpM = wid >> 1;         // 0..3 (32 rows each)
    const int warpN = wid & 1;          // 0..1 (32 cols each)
    const int b = blockIdx.z;
    const int mBase = blockIdx.y * 128;
    const int oy = blockIdx.x;          // output row
    const int nBase = blockIdx.x * 64;

    // ---- A staging: am row 0..127, half of 64-col chunk ----
    const int am = tid >> 1;
    const int ahalf = tid & 1;
    const long aSrcBase = (long)(b * 256 + mBase + am) * 2304 + ahalf * 32;
    const int am7 = am & 7;
    const int aDstRow = am * 128;

    // ---- B staging: icl k-row 0..63, q = col quarter (16 cols each) ----
    const int icl = tid >> 2;
    const int q = tid & 3;
    const int icl7 = icl & 7;
    const int bDstRow = icl * 128;

    // ---- fragment constants ----
    const int laneRow = lane & 15;
    const int laneSel = lane >> 4;
    const int mW = warpM * 32;
    const int nW = warpN * 32;
    int mRowB[2], mRow7[2];
#pragma unroll
    for (int mt = 0; mt < 2; mt++) {
        int m = mW + mt * 16 + laneRow;
        mRowB[mt] = m * 128;
        mRow7[mt] = m & 7;
    }
    const int bKRow = laneRow * 128;
    const int bK7 = laneRow & 7;
    int bUn[2];
#pragma unroll
    for (int nt2 = 0; nt2 < 2; nt2++)
        bUn[nt2] = warpN * 4 + nt2 * 2 + laneSel;   // 0..7

    float acc[2][4][4];
#pragma unroll
    for (int i = 0; i < 2; i++)
#pragma unroll
        for (int j = 0; j < 4; j++)
#pragma unroll
            for (int k = 0; k < 4; k++) acc[i][j][k] = 0.f;

    uint32_t bq[16];

    auto issueA = [&](int stage, int chunk) {
        const __nv_bfloat16* sh = g_wAb_hi + aSrcBase + chunk * 64;
        const __nv_bfloat16* sl = g_wAb_lo + aSrcBase + chunk * 64;
        uint32_t dh = sb + SA_H(stage) + aDstRow;
        uint32_t dl = sb + SA_L(stage) + aDstRow;
#pragma unroll
        for (int j = 0; j < 4; j++) {
            int u = ahalf * 4 + j;
            int sw = ((u ^ am7) & 7) * 16;
            CP_ASYNC16(dh + sw, sh + j * 8);
            CP_ASYNC16(dl + sw, sl + j * 8);
        }
    };
    auto issueB = [&](int chunk) {
        int tap = chunk >> 2;
        int icq = chunk & 3;
        int ty = (tap >= 6) ? 2 : (tap >= 3 ? 1 : 0);
        int tx = tap - ty * 3;
        int py = (ty == 1) ? 0 : 1;
        int px = (tx == 1) ? 0 : 1;
        int row = oy + (ty != 0);
        int colBase = q * 16 + (tx != 0);
        const unsigned* src = g_pp
            + ((long)((b * 2 + py) * 2 + px) * 256 + icq * 64 + icl) * (long)PP_PLANE
            + row * 72 + colBase;
#pragma unroll
        for (int j = 0; j < 16; j++) bq[j] = src[j];
    };
    auto storeB_g = [&](int stage, int g) {
        char* bh = smem + SB_H(stage);
        char* bl = smem + SB_L(stage);
        int u = q * 2 + g;
        int off = bDstRow + ((u ^ icl7) & 7) * 16;
        uint4 vh, vl;
        vh.x = __byte_perm(bq[g * 8 + 0], bq[g * 8 + 1], 0x7632);
        vl.x = __byte_perm(bq[g * 8 + 0], bq[g * 8 + 1], 0x5410);
        vh.y = __byte_perm(bq[g * 8 + 2], bq[g * 8 + 3], 0x7632);
        vl.y = __byte_perm(bq[g * 8 + 2], bq[g * 8 + 3], 0x5410);
        vh.z = __byte_perm(bq[g * 8 + 4], bq[g * 8 + 5], 0x7632);
        vl.z = __byte_perm(bq[g * 8 + 4], bq[g * 8 + 5], 0x5410);
        vh.w = __byte_perm(bq[g * 8 + 6], bq[g * 8 + 7], 0x7632);
        vl.w = __byte_perm(bq[g * 8 + 6], bq[g * 8 + 7], 0x5410);
        *reinterpret_cast<uint4*>(bh + off) = vh;
        *reinterpret_cast<uint4*>(bl + off) = vl;
    };

    // ===== prologue =====
    issueB(0);
    issueA(0, 0);
    CP_COMMIT();
    storeB_g(0, 0);
    storeB_g(0, 1);
    CP_WAIT_ALL();
    __syncthreads();

    // ===== mainloop =====
    for (int chunk = 0; chunk < 36; ++chunk) {
        const int cur = chunk & 1;
        const bool hasNext = (chunk + 1 < 36);
        if (hasNext) {
            issueB(chunk + 1);
            issueA(cur ^ 1, chunk + 1);
            CP_COMMIT();
        }

        const uint32_t aH_base = sb + SA_H(cur);
        const uint32_t aL_base = sb + SA_L(cur);
        const uint32_t bH_base = sb + SB_H(cur);
        const uint32_t bL_base = sb + SB_L(cur);

#pragma unroll
        for (int kk = 0; kk < 4; kk++) {
            uint32_t aH[2][4], aL[2][4], bH[2][4], bL[2][4];
#pragma unroll
            for (int mt = 0; mt < 2; mt++) {
                int u = kk * 2 + laneSel;
                int off = mRowB[mt] + ((u ^ mRow7[mt]) & 7) * 16;
                ldmat_x4(aH[mt], aH_base + off);
                ldmat_x4(aL[mt], aL_base + off);
            }
#pragma unroll
            for (int nt2 = 0; nt2 < 2; nt2++) {
                int off = kk * 16 * 128 + bKRow + ((bUn[nt2] ^ bK7) & 7) * 16;
                ldmat_x4_t(bH[nt2], bH_base + off);
                ldmat_x4_t(bL[nt2], bL_base + off);
            }
#pragma unroll
            for (int mt = 0; mt < 2; mt++) {
#pragma unroll
                for (int nt = 0; nt < 4; nt++) {
                    int nt2 = nt >> 1, sub = (nt & 1) * 2;
                    mma16816(acc[mt][nt], aH[mt], bH[nt2][sub], bH[nt2][sub + 1]);
                    mma16816(acc[mt][nt], aH[mt], bL[nt2][sub], bL[nt2][sub + 1]);
                    mma16816(acc[mt][nt], aL[mt], bH[nt2][sub], bH[nt2][sub + 1]);
                }
            }
            // hide next-stage STS late (gives B LDGs latency cover)
            if (hasNext && kk >= 2) storeB_g(cur ^ 1, kk - 2);
        }

        CP_WAIT_ALL();
        __syncthreads();
    }

    // ===== epilogue: alpha, bias, scaled LeakyReLU =====
    const int rowInTile = lane >> 2;
    const int colInTile = (lane & 3) * 2;
#pragma unroll
    for (int mt = 0; mt < 2; mt++) {
        int o0 = mBase + mW + mt * 16 + rowInTile;
        int o1 = o0 + 8;
        float al0 = g_alpha[b * 256 + o0], bi0 = conv_b[o0];
        float al1 = g_alpha[b * 256 + o1], bi1 = conv_b[o1];
        float* p0 = out + (long)(b * 256 + o0) * 4096 + nBase + nW + colInTile;
        float* p1 = out + (long)(b * 256 + o1) * 4096 + nBase + nW + colInTile;
#pragma unroll
        for (int nt = 0; nt < 4; nt++) {
            float2 v0, v1;
            float v;
            v = acc[mt][nt][0] * al0 + bi0;
            v0.x = (v >= 0.f ? v : LRELU_SLOPE * v) * SQRT2F;
            v = acc[mt][nt][1] * al0 + bi0;
            v0.y = (v >= 0.f ? v : LRELU_SLOPE * v) * SQRT2F;
            v = acc[mt][nt][2] * al1 + bi1;
            v1.x = (v >= 0.f ? v : LRELU_SLOPE * v) * SQRT2F;
            v = acc[mt][nt][3] * al1 + bi1;
            v1.y = (v >= 0.f ? v : LRELU_SLOPE * v) * SQRT2F;
            *reinterpret_cast<float2*>(p0 + nt * 8) = v0;
            *reinterpret_cast<float2*>(p1 + nt * 8) = v1;
        }
    }
}

// ============================ launch ============================
extern "C" void kernel_launch(void* const* d_in, const int* in_sizes, int n_in,
                              void* d_out, int out_size) {
    const float* x       = (const float*)d_in[0];  // [8,256,128,128]
    const float* s       = (const float*)d_in[1];  // [8,512]
    const float* conv_w  = (const float*)d_in[2];  // [256,256,3,3]
    const float* conv_b  = (const float*)d_in[3];  // [256]
    const float* style_w = (const float*)d_in[4];  // [256,512]
    const float* style_b = (const float*)d_in[5];  // [256]
    const float* norm_g  = (const float*)d_in[6];  // [256]
    float* out = (float*)d_out;                    // [8,256,64,64]

    static int attr_set = 0;
    if (!attr_set) {
        cudaFuncSetAttribute(mma_conv_kernel,
                             cudaFuncAttributeMaxDynamicSharedMemorySize, CONV_SMEM);
        cudaFuncSetAttribute(blur_kernel,
                             cudaFuncAttributeMaxDynamicSharedMemorySize, BLUR_SMEM);
        attr_set = 1;
    }

    style_kernel<<<256, 256>>>(s, style_w, style_b);                    // launch 1
    blur_kernel<<<4224, 256, BLUR_SMEM>>>(x);                          // launch 2
    wsplit_kernel<<<dim3(256, 8), 256>>>(conv_w, norm_g);              // launch 3
    mma_conv_kernel<<<dim3(64, 2, 8), 256, CONV_SMEM>>>(conv_b, out);  // launch 4
}

// round 8
// speedup vs baseline: 2.6523x; 1.3097x over previous
#include <cuda_runtime.h>
#include <cuda_bf16.h>
#include <cstdint>

// ============================ helpers ============================
__device__ __forceinline__ uint32_t smem_to_u32(const void* smem_ptr) {
    uint32_t addr;
    asm("{ .reg .u64 tmp; cvta.to.shared.u64 tmp, %1; cvt.u32.u64 %0, tmp; }"
        : "=r"(addr) : "l"(smem_ptr));
    return addr;
}

#define CP_ASYNC16(dst, src) \
    asm volatile("cp.async.cg.shared.global [%0], [%1], 16;" \
                 :: "r"(dst), "l"(src) : "memory")
#define CP_COMMIT() asm volatile("cp.async.commit_group;" ::: "memory")
#define CP_WAIT_ALL() asm volatile("cp.async.wait_group 0;" ::: "memory")

__device__ __forceinline__ void ldmat_x4(uint32_t* r, uint32_t addr) {
    asm volatile("ldmatrix.sync.aligned.m8n8.x4.shared.b16 {%0,%1,%2,%3}, [%4];"
                 : "=r"(r[0]), "=r"(r[1]), "=r"(r[2]), "=r"(r[3]) : "r"(addr));
}
__device__ __forceinline__ void ldmat_x4_t(uint32_t* r, uint32_t addr) {
    asm volatile("ldmatrix.sync.aligned.m8n8.x4.trans.shared.b16 {%0,%1,%2,%3}, [%4];"
                 : "=r"(r[0]), "=r"(r[1]), "=r"(r[2]), "=r"(r[3]) : "r"(addr));
}
__device__ __forceinline__ void mma16816(float* c, const uint32_t* a,
                                         uint32_t b0, uint32_t b1) {
    asm volatile(
        "mma.sync.aligned.m16n8k16.row.col.f32.bf16.bf16.f32 "
        "{%0,%1,%2,%3}, {%4,%5,%6,%7}, {%8,%9}, {%0,%1,%2,%3};"
        : "+f"(c[0]), "+f"(c[1]), "+f"(c[2]), "+f"(c[3])
        : "r"(a[0]), "r"(a[1]), "r"(a[2]), "r"(a[3]), "r"(b0), "r"(b1));
}

// ============================ scratch globals ============================
// parity planes, packed u32 = (bf16_hi << 16) | bf16_lo of blurred x
// layout [b][py][px][ic][65 rows][72 cols]; row 0 / col 0 are zero borders
#define PP_PLANE 4680  // 65*72
__device__ unsigned g_pp[8L * 2 * 2 * 256 * PP_PLANE];   // ~153 MB
__device__ float g_style[8 * 256];
__device__ float g_partial[4096];
__device__ float g_alpha[8 * 256];
// per-batch scaled weights, reordered k = t*256+ic, split bf16 hi/lo
__device__ __align__(256) __nv_bfloat16 g_wAb_hi[8L * 256 * 2304];
__device__ __align__(256) __nv_bfloat16 g_wAb_lo[8L * 256 * 2304];

#define LRELU_SLOPE 0.2f
#define SQRT2F 1.41421356237309515f

// ============================ K1: style ============================
__global__ void style_kernel(const float* __restrict__ s,
                             const float* __restrict__ style_w,
                             const float* __restrict__ style_b) {
    int wg = blockIdx.x * 8 + (threadIdx.x >> 5);
    int lane = threadIdx.x & 31;
    int b = wg >> 8, i = wg & 255;
    const float* sp = s + b * 512;
    const float* wp = style_w + i * 512;
    float acc = 0.f;
#pragma unroll 4
    for (int j = lane; j < 512; j += 32) acc += sp[j] * wp[j];
#pragma unroll
    for (int o = 16; o; o >>= 1) acc += __shfl_xor_sync(0xffffffffu, acc, o);
    if (lane == 0) g_style[wg] = acc + style_b[i];
}

// ============================ K2: blur + borders ============================
#define BLUR_IN_W 136
#define BLUR_SMEM ((68 * BLUR_IN_W + 68 * 128 + 8) * 4)

__global__ __launch_bounds__(256) void blur_kernel(const float* __restrict__ x) {
    if (blockIdx.x >= 4096) {
        int base = (blockIdx.x - 4096) * 256 + threadIdx.x;
        for (long idx = base; idx < 8192L * 144; idx += 32768) {
            long plane = idx / 144;
            int e = (int)(idx - plane * 144);
            unsigned* p = g_pp + plane * PP_PLANE;
            if (e < 72) p[e] = 0u;
            else if (e < 137) p[(e - 72) * 72] = 0u;
        }
        return;
    }

    extern __shared__ __align__(16) float sm[];
    float* in = sm;                     // [68][136], data at cols 4..131
    float* hb = sm + 68 * BLUR_IN_W;    // [68][128]
    float* red = hb + 68 * 128;

    const int plane = blockIdx.x >> 1;
    const int b = plane >> 8, c = plane & 255;
    const int h0 = (blockIdx.x & 1) * 64;
    const int tid = threadIdx.x;
    const float* xp = x + (long)plane * 16384;

    for (int t = tid; t < 544; t += 256) {
        int r = t >> 3, j = t & 7;
        in[r * BLUR_IN_W + (j < 4 ? j : 128 + j)] = 0.f;
    }
    for (int pos = tid; pos < 68 * 32; pos += 256) {
        int r = pos >> 5, c4 = pos & 31;
        int h = h0 - 2 + r;
        float4 v = make_float4(0.f, 0.f, 0.f, 0.f);
        if ((unsigned)h < 128u)
            v = *reinterpret_cast<const float4*>(xp + h * 128 + c4 * 4);
        *reinterpret_cast<float4*>(in + r * BLUR_IN_W + 4 + c4 * 4) = v;
    }
    __syncthreads();

    for (int pos = tid; pos < 68 * 32; pos += 256) {
        int r = pos >> 5, c4 = pos & 31;
        const float* row = in + r * BLUR_IN_W + c4 * 4;
        float4 a = *reinterpret_cast<const float4*>(row);
        float4 bb = *reinterpret_cast<const float4*>(row + 4);
        float4 cc = *reinterpret_cast<const float4*>(row + 8);
        float4 o;
        o.x = a.z + 4.f * a.w + 6.f * bb.x + 4.f * bb.y + bb.z;
        o.y = a.w + 4.f * bb.x + 6.f * bb.y + 4.f * bb.z + bb.w;
        o.z = bb.x + 4.f * bb.y + 6.f * bb.z + 4.f * bb.w + cc.x;
        o.w = bb.y + 4.f * bb.z + 6.f * bb.w + 4.f * cc.x + cc.y;
        *reinterpret_cast<float4*>(hb + r * 128 + c4 * 4) = o;
    }
    __syncthreads();

    float ss = 0.f;
    for (int pos = tid; pos < 64 * 32; pos += 256) {
        int r = pos >> 5, c4 = pos & 31;
        const float* col = hb + r * 128 + c4 * 4;
        float4 h0v = *reinterpret_cast<const float4*>(col);
        float4 h1v = *reinterpret_cast<const float4*>(col + 128);
        float4 h2v = *reinterpret_cast<const float4*>(col + 256);
        float4 h3v = *reinterpret_cast<const float4*>(col + 384);
        float4 h4v = *reinterpret_cast<const float4*>(col + 512);
        float v0 = (h0v.x + 4.f * h1v.x + 6.f * h2v.x + 4.f * h3v.x + h4v.x) * (1.f / 256.f);
        float v1 = (h0v.y + 4.f * h1v.y + 6.f * h2v.y + 4.f * h3v.y + h4v.y) * (1.f / 256.f);
        float v2 = (h0v.z + 4.f * h1v.z + 6.f * h2v.z + 4.f * h3v.z + h4v.z) * (1.f / 256.f);
        float v3 = (h0v.w + 4.f * h1v.w + 6.f * h2v.w + 4.f * h3v.w + h4v.w) * (1.f / 256.f);
        ss += v0 * v0 + v1 * v1 + v2 * v2 + v3 * v3;

        auto pack = [](float v) -> unsigned {
            __nv_bfloat16 h16 = __float2bfloat16(v);
            __nv_bfloat16 l16 = __float2bfloat16(v - __bfloat162float(h16));
            return ((unsigned)__bfloat16_as_ushort(h16) << 16)
                 | (unsigned)__bfloat16_as_ushort(l16);
        };
        unsigned p0 = pack(v0), p1 = pack(v1), p2 = pack(v2), p3 = pack(v3);

        int iy = h0 + r;
        int py = iy & 1;
        int prow = (iy >> 1) + 1;
        int col0 = 2 * c4 + 1;
        unsigned* d0 = g_pp + ((long)((b * 2 + py) * 2 + 0) * 256 + c) * PP_PLANE
                      + prow * 72 + col0;
        unsigned* d1 = g_pp + ((long)((b * 2 + py) * 2 + 1) * 256 + c) * PP_PLANE
                      + prow * 72 + col0;
        d0[0] = p0; d0[1] = p2;
        d1[0] = p1; d1[1] = p3;
    }
#pragma unroll
    for (int o = 16; o; o >>= 1) ss += __shfl_xor_sync(0xffffffffu, ss, o);
    if ((tid & 31) == 0) red[tid >> 5] = ss;
    __syncthreads();
    if (tid == 0) {
        float t = 0.f;
#pragma unroll
        for (int k = 0; k < 8; k++) t += red[k];
        g_partial[blockIdx.x] = t;
    }
}

// ============================ K3: wsplit + rscale + alpha ============================
__global__ __launch_bounds__(256) void wsplit_kernel(const float* __restrict__ w,
                                                     const float* __restrict__ norm_g) {
    __shared__ float ws[2304];
    __shared__ float rs[256];
    __shared__ float red[8];
    const int o = blockIdx.x;
    const int b = blockIdx.y;
    const int tid = threadIdx.x;

    const float4* wsrc = reinterpret_cast<const float4*>(w + (long)o * 2304);
    for (int i = tid; i < 576; i += 256)
        *reinterpret_cast<float4*>(ws + i * 4) = wsrc[i];

    {
        int p = b * 256 + tid;
        float ssum = g_partial[2 * p] + g_partial[2 * p + 1];
        float ms = ssum * (1.f / 16384.f);
        rs[tid] = rsqrtf(ms + 1e-8f) * norm_g[tid] * g_style[p];
    }
    __syncthreads();

    {
        float sv = g_style[b * 256 + tid];
        float wq = 0.f;
#pragma unroll
        for (int t = 0; t < 9; t++) { float v = ws[tid * 9 + t]; wq += v * v; }
        float pa = sv * sv * wq;
#pragma unroll
        for (int off = 16; off; off >>= 1) pa += __shfl_xor_sync(0xffffffffu, pa, off);
        if ((tid & 31) == 0) red[tid >> 5] = pa;
    }

    {
        const float rsc = rs[tid];
        long dstBase = (long)(b * 256 + o) * 2304 + tid;
#pragma unroll
        for (int t = 0; t < 9; t++) {
            float v = ws[tid * 9 + t] * rsc;
            __nv_bfloat16 h = __float2bfloat16(v);
            g_wAb_hi[dstBase + t * 256] = h;
            g_wAb_lo[dstBase + t * 256] = __float2bfloat16(v - __bfloat162float(h));
        }
    }

    __syncthreads();
    if (tid == 0) {
        float acc = 0.f;
#pragma unroll
        for (int k = 0; k < 8; k++) acc += red[k];
        const float sc = 1.f / 48.f;  // 1/sqrt(256*9)
        g_alpha[b * 256 + o] = sc * rsqrtf(sc * sc * acc + 1e-8f);
    }
}

// ============================ K4: HMMA conv GEMM ============================
// CTA tile: M=128 (o), N=64 (one output row). grid (64,2,8).
// K = 2304 = 36 chunks of 64 (k = t*256+ic). bf16 split: C = AhiBhi+AhiBlo+AloBhi
// B staging: warp-per-ic-row coalesced uint2 loads + shfl column shift.
// smem: A hi/lo 16+16KB, B hi/lo 8+8KB, double-buffered = 96KB -> 2 CTAs/SM.

#define SA_H(st) ((st) * 16384)
#define SA_L(st) (32768 + (st) * 16384)
#define SB_H(st) (65536 + (st) * 8192)
#define SB_L(st) (81920 + (st) * 8192)
#define CONV_SMEM 98304

__global__ __launch_bounds__(256, 2)
void mma_conv_kernel(const float* __restrict__ conv_b, float* __restrict__ out) {
    extern __shared__ __align__(1024) char smem[];
    const uint32_t sb = smem_to_u32(smem);
    const int tid = threadIdx.x;
    const int lane = tid & 31;
    const int wid = tid >> 5;
    const int warpM = wid >> 1;         // 0..3 (32 rows each)
    const int warpN = wid & 1;          // 0..1 (32 cols each)
    const int b = blockIdx.z;
    const int mBase = blockIdx.y * 128;
    const int oy = blockIdx.x;          // output row
    const int nBase = blockIdx.x * 64;

    // ---- A staging: 8 lanes per row-line; thread -> (unit aj, row ar0+32p) ----
    const int aj = tid & 7;
    const int ar0 = tid >> 3;           // 0..31

    // ---- fragment constants ----
    const int laneRow = lane & 15;
    const int laneSel = lane >> 4;
    const int mW = warpM * 32;
    const int nW = warpN * 32;
    int mRowB[2], mRow7[2];
#pragma unroll
    for (int mt = 0; mt < 2; mt++) {
        int m = mW + mt * 16 + laneRow;
        mRowB[mt] = m * 128;
        mRow7[mt] = m & 7;
    }
    const int bKRow = laneRow * 128;
    const int bK7 = laneRow & 7;
    int bUn[2];
#pragma unroll
    for (int nt2 = 0; nt2 < 2; nt2++)
        bUn[nt2] = warpN * 4 + nt2 * 2 + laneSel;   // 0..7

    float acc[2][4][4];
#pragma unroll
    for (int i = 0; i < 2; i++)
#pragma unroll
        for (int j = 0; j < 4; j++)
#pragma unroll
            for (int k = 0; k < 4; k++) acc[i][j][k] = 0.f;

    // B staging state: 4 ic-rows per batch, already column-shifted
    uint2 bv[4];

    auto issueA = [&](int stage, int chunk) {
#pragma unroll
        for (int p = 0; p < 4; p++) {
            int r = ar0 + 32 * p;
            long src = (long)(b * 256 + mBase + r) * 2304 + chunk * 64 + aj * 8;
            int sw = r * 128 + ((aj ^ (r & 7)) & 7) * 16;
            CP_ASYNC16(sb + SA_H(stage) + sw, g_wAb_hi + src);
            CP_ASYNC16(sb + SA_L(stage) + sw, g_wAb_lo + src);
        }
    };
    // load 4 ic-rows (h-th half) of chunk's B tile, coalesced, apply tap shift
    auto loadB4 = [&](int chunk, int h) {
        int tap = chunk >> 2;
        int icq = chunk & 3;
        int ty = (tap >= 6) ? 2 : (tap >= 3 ? 1 : 0);
        int tx = tap - ty * 3;
        int py = (ty == 1) ? 0 : 1;
        int px = (tx == 1) ? 0 : 1;
        int shift = (tx != 0);
        int row = oy + (ty != 0);
        const unsigned* pb = g_pp
            + ((long)((b * 2 + py) * 2 + px) * 256 + icq * 64) * (long)PP_PLANE
            + row * 72;
        uint2 tv[4];
        unsigned tex[4];
#pragma unroll
        for (int p = 0; p < 4; p++) {
            const unsigned* src = pb + (long)((h * 4 + p) * 8 + wid) * PP_PLANE;
            tv[p] = *reinterpret_cast<const uint2*>(src + 2 * lane);
            tex[p] = (lane == 31) ? src[64] : 0u;
        }
#pragma unroll
        for (int p = 0; p < 4; p++) {
            unsigned nx = __shfl_down_sync(0xffffffffu, tv[p].x, 1);
            if (lane == 31) nx = tex[p];
            bv[p].x = shift ? tv[p].y : tv[p].x;
            bv[p].y = shift ? nx : tv[p].y;
        }
    };
    // store row p of current batch (half h) into stage buffers (hi/lo split)
    auto storeB_p = [&](int stage, int h, int p) {
        int ic = (h * 4 + p) * 8 + wid;
        unsigned hp = __byte_perm(bv[p].x, bv[p].y, 0x7632);
        unsigned lp = __byte_perm(bv[p].x, bv[p].y, 0x5410);
        int u = lane >> 2;
        int off = ic * 128 + ((u ^ (ic & 7)) & 7) * 16 + (lane & 3) * 4;
        *reinterpret_cast<unsigned*>(smem + SB_H(stage) + off) = hp;
        *reinterpret_cast<unsigned*>(smem + SB_L(stage) + off) = lp;
    };

    // ===== prologue: fill stage 0 =====
    issueA(0, 0);
    CP_COMMIT();
    loadB4(0, 0);
#pragma unroll
    for (int p = 0; p < 4; p++) storeB_p(0, 0, p);
    loadB4(0, 1);
#pragma unroll
    for (int p = 0; p < 4; p++) storeB_p(0, 1, p);
    CP_WAIT_ALL();
    __syncthreads();

    // ===== mainloop =====
    for (int chunk = 0; chunk < 36; ++chunk) {
        const int cur = chunk & 1;
        const int nxt = cur ^ 1;
        const bool hasNext = (chunk + 1 < 36);
        if (hasNext) {
            issueA(nxt, chunk + 1);
            CP_COMMIT();
            loadB4(chunk + 1, 0);
        }

        const uint32_t aH_base = sb + SA_H(cur);
        const uint32_t aL_base = sb + SA_L(cur);
        const uint32_t bH_base = sb + SB_H(cur);
        const uint32_t bL_base = sb + SB_L(cur);

#pragma unroll
        for (int kk = 0; kk < 4; kk++) {
            uint32_t aH[2][4], aL[2][4], bH[2][4], bL[2][4];
#pragma unroll
            for (int mt = 0; mt < 2; mt++) {
                int u = kk * 2 + laneSel;
                int off = mRowB[mt] + ((u ^ mRow7[mt]) & 7) * 16;
                ldmat_x4(aH[mt], aH_base + off);
                ldmat_x4(aL[mt], aL_base + off);
            }
#pragma unroll
            for (int nt2 = 0; nt2 < 2; nt2++) {
                int off = kk * 16 * 128 + bKRow + ((bUn[nt2] ^ bK7) & 7) * 16;
                ldmat_x4_t(bH[nt2], bH_base + off);
                ldmat_x4_t(bL[nt2], bL_base + off);
            }
#pragma unroll
            for (int mt = 0; mt < 2; mt++) {
#pragma unroll
                for (int nt = 0; nt < 4; nt++) {
                    int nt2 = nt >> 1, sub = (nt & 1) * 2;
                    mma16816(acc[mt][nt], aH[mt], bH[nt2][sub], bH[nt2][sub + 1]);
                    mma16816(acc[mt][nt], aH[mt], bL[nt2][sub], bL[nt2][sub + 1]);
                    mma16816(acc[mt][nt], aL[mt], bH[nt2][sub], bH[nt2][sub + 1]);
                }
            }
            if (hasNext) {
                if (kk == 0) { storeB_p(nxt, 0, 0); storeB_p(nxt, 0, 1); }
                else if (kk == 1) {
                    storeB_p(nxt, 0, 2); storeB_p(nxt, 0, 3);
                    loadB4(chunk + 1, 1);
                } else if (kk == 2) { storeB_p(nxt, 1, 0); storeB_p(nxt, 1, 1); }
                else { storeB_p(nxt, 1, 2); storeB_p(nxt, 1, 3); }
            }
        }

        CP_WAIT_ALL();
        __syncthreads();
    }

    // ===== epilogue: alpha, bias, scaled LeakyReLU =====
    const int rowInTile = lane >> 2;
    const int colInTile = (lane & 3) * 2;
#pragma unroll
    for (int mt = 0; mt < 2; mt++) {
        int o0 = mBase + mW + mt * 16 + rowInTile;
        int o1 = o0 + 8;
        float al0 = g_alpha[b * 256 + o0], bi0 = conv_b[o0];
        float al1 = g_alpha[b * 256 + o1], bi1 = conv_b[o1];
        float* p0 = out + (long)(b * 256 + o0) * 4096 + nBase + nW + colInTile;
        float* p1 = out + (long)(b * 256 + o1) * 4096 + nBase + nW + colInTile;
#pragma unroll
        for (int nt = 0; nt < 4; nt++) {
            float2 v0, v1;
            float v;
            v = acc[mt][nt][0] * al0 + bi0;
            v0.x = (v >= 0.f ? v : LRELU_SLOPE * v) * SQRT2F;
            v = acc[mt][nt][1] * al0 + bi0;
            v0.y = (v >= 0.f ? v : LRELU_SLOPE * v) * SQRT2F;
            v = acc[mt][nt][2] * al1 + bi1;
            v1.x = (v >= 0.f ? v : LRELU_SLOPE * v) * SQRT2F;
            v = acc[mt][nt][3] * al1 + bi1;
            v1.y = (v >= 0.f ? v : LRELU_SLOPE * v) * SQRT2F;
            *reinterpret_cast<float2*>(p0 + nt * 8) = v0;
            *reinterpret_cast<float2*>(p1 + nt * 8) = v1;
        }
    }
}

// ============================ launch ============================
extern "C" void kernel_launch(void* const* d_in, const int* in_sizes, int n_in,
                              void* d_out, int out_size) {
    const float* x       = (const float*)d_in[0];  // [8,256,128,128]
    const float* s       = (const float*)d_in[1];  // [8,512]
    const float* conv_w  = (const float*)d_in[2];  // [256,256,3,3]
    const float* conv_b  = (const float*)d_in[3];  // [256]
    const float* style_w = (const float*)d_in[4];  // [256,512]
    const float* style_b = (const float*)d_in[5];  // [256]
    const float* norm_g  = (const float*)d_in[6];  // [256]
    float* out = (float*)d_out;                    // [8,256,64,64]

    static int attr_set = 0;
    if (!attr_set) {
        cudaFuncSetAttribute(mma_conv_kernel,
                             cudaFuncAttributeMaxDynamicSharedMemorySize, CONV_SMEM);
        cudaFuncSetAttribute(blur_kernel,
                             cudaFuncAttributeMaxDynamicSharedMemorySize, BLUR_SMEM);
        attr_set = 1;
    }

    style_kernel<<<256, 256>>>(s, style_w, style_b);                    // launch 1
    blur_kernel<<<4224, 256, BLUR_SMEM>>>(x);                          // launch 2
    wsplit_kernel<<<dim3(256, 8), 256>>>(conv_w, norm_g);              // launch 3
    mma_conv_kernel<<<dim3(64, 2, 8), 256, CONV_SMEM>>>(conv_b, out);  // launch 4
}

// round 9
// speedup vs baseline: 3.2333x; 1.2191x over previous
#include <cuda_runtime.h>
#include <cuda_bf16.h>
#include <cstdint>

// ============================ helpers ============================
__device__ __forceinline__ uint32_t smem_to_u32(const void* smem_ptr) {
    uint32_t addr;
    asm("{ .reg .u64 tmp; cvta.to.shared.u64 tmp, %1; cvt.u32.u64 %0, tmp; }"
        : "=r"(addr) : "l"(smem_ptr));
    return addr;
}

#define CP_ASYNC16(dst, src) \
    asm volatile("cp.async.cg.shared.global [%0], [%1], 16;" \
                 :: "r"(dst), "l"(src) : "memory")
#define CP_COMMIT() asm volatile("cp.async.commit_group;" ::: "memory")
#define CP_WAIT_ALL() asm volatile("cp.async.wait_group 0;" ::: "memory")

__device__ __forceinline__ void ldmat_x4(uint32_t* r, uint32_t addr) {
    asm volatile("ldmatrix.sync.aligned.m8n8.x4.shared.b16 {%0,%1,%2,%3}, [%4];"
                 : "=r"(r[0]), "=r"(r[1]), "=r"(r[2]), "=r"(r[3]) : "r"(addr));
}
__device__ __forceinline__ void ldmat_x4_t(uint32_t* r, uint32_t addr) {
    asm volatile("ldmatrix.sync.aligned.m8n8.x4.trans.shared.b16 {%0,%1,%2,%3}, [%4];"
                 : "=r"(r[0]), "=r"(r[1]), "=r"(r[2]), "=r"(r[3]) : "r"(addr));
}
__device__ __forceinline__ void mma16816(float* c, const uint32_t* a,
                                         uint32_t b0, uint32_t b1) {
    asm volatile(
        "mma.sync.aligned.m16n8k16.row.col.f32.bf16.bf16.f32 "
        "{%0,%1,%2,%3}, {%4,%5,%6,%7}, {%8,%9}, {%0,%1,%2,%3};"
        : "+f"(c[0]), "+f"(c[1]), "+f"(c[2]), "+f"(c[3])
        : "r"(a[0]), "r"(a[1]), "r"(a[2]), "r"(a[3]), "r"(b0), "r"(b1));
}

// ============================ scratch globals ============================
// Pre-split, pre-shifted bf16 planes of the blurred input.
// Layout: [b][py][pvar][ic][row 0..64][col 0..63], row pitch 64 bf16 = 128B.
//   pvar 0: px=1 values, col c holds x(ix=2c-1)   (tap tx=0 reads col=ox; col0 = zero border)
//   pvar 1: px=1 values, col c holds x(ix=2c+1)   (tap tx=2 reads col=ox)
//   pvar 2: px=0 values, col c holds x(ix=2c)     (tap tx=1 reads col=ox)
// Row r holds iy = 2r-2+py... (reads: ty=0 -> py=1,row=oy; ty=1 -> py=0,row=oy+1; ty=2 -> py=1,row=oy+1)
#define PL_SIZE 4160  // 65*64
__device__ __nv_bfloat16 g_ph[8L * 2 * 3 * 256 * PL_SIZE];  // hi, ~102 MB
__device__ __nv_bfloat16 g_pl[8L * 2 * 3 * 256 * PL_SIZE];  // lo, ~102 MB
__device__ float g_style[8 * 256];
__device__ float g_partial[4096];
__device__ float g_alpha[8 * 256];
// per-batch scaled weights, reordered k = t*256+ic, split bf16 hi/lo
__device__ __align__(256) __nv_bfloat16 g_wAb_hi[8L * 256 * 2304];
__device__ __align__(256) __nv_bfloat16 g_wAb_lo[8L * 256 * 2304];

#define LRELU_SLOPE 0.2f
#define SQRT2F 1.41421356237309515f

// ============================ K1: style ============================
__global__ void style_kernel(const float* __restrict__ s,
                             const float* __restrict__ style_w,
                             const float* __restrict__ style_b) {
    int wg = blockIdx.x * 8 + (threadIdx.x >> 5);
    int lane = threadIdx.x & 31;
    int b = wg >> 8, i = wg & 255;
    const float* sp = s + b * 512;
    const float* wp = style_w + i * 512;
    float acc = 0.f;
#pragma unroll 4
    for (int j = lane; j < 512; j += 32) acc += sp[j] * wp[j];
#pragma unroll
    for (int o = 16; o; o >>= 1) acc += __shfl_xor_sync(0xffffffffu, acc, o);
    if (lane == 0) g_style[wg] = acc + style_b[i];
}

// ============================ K2: blur + split + borders ============================
#define BLUR_IN_W 136
#define BLUR_SMEM ((68 * BLUR_IN_W + 68 * 128 + 8) * 4)

__global__ __launch_bounds__(256) void blur_kernel(const float* __restrict__ x) {
    if (blockIdx.x >= 4096) {
        // border zeroing (py=1 set): pvar0 row0 (64), pvar0 col0 (65), pvar1 row0 (64)
        long base = (long)(blockIdx.x - 4096) * 256 + threadIdx.x;   // 32768 threads
        const __nv_bfloat16 z = __float2bfloat16(0.f);
        for (long idx = base; idx < 2048L * 208; idx += 32768) {
            int pair = (int)(idx / 208);
            int e = (int)(idx - (long)pair * 208);
            int bb = pair >> 8, ic = pair & 255;
            long p0 = ((long)((bb * 2 + 1) * 3 + 0) * 256 + ic) * PL_SIZE;
            long p1 = ((long)((bb * 2 + 1) * 3 + 1) * 256 + ic) * PL_SIZE;
            if (e < 64)       { g_ph[p0 + e] = z;            g_pl[p0 + e] = z; }
            else if (e < 129) { int r = e - 64;  g_ph[p0 + r * 64] = z; g_pl[p0 + r * 64] = z; }
            else if (e < 193) { int cc = e - 129; g_ph[p1 + cc] = z;   g_pl[p1 + cc] = z; }
        }
        return;
    }

    extern __shared__ __align__(16) float sm[];
    float* in = sm;                     // [68][136], data at cols 4..131
    float* hb = sm + 68 * BLUR_IN_W;    // [68][128]
    float* red = hb + 68 * 128;

    const int plane = blockIdx.x >> 1;
    const int b = plane >> 8, c = plane & 255;
    const int h0 = (blockIdx.x & 1) * 64;
    const int tid = threadIdx.x;
    const float* xp = x + (long)plane * 16384;

    for (int t = tid; t < 544; t += 256) {
        int r = t >> 3, j = t & 7;
        in[r * BLUR_IN_W + (j < 4 ? j : 128 + j)] = 0.f;
    }
    for (int pos = tid; pos < 68 * 32; pos += 256) {
        int r = pos >> 5, c4 = pos & 31;
        int h = h0 - 2 + r;
        float4 v = make_float4(0.f, 0.f, 0.f, 0.f);
        if ((unsigned)h < 128u)
            v = *reinterpret_cast<const float4*>(xp + h * 128 + c4 * 4);
        *reinterpret_cast<float4*>(in + r * BLUR_IN_W + 4 + c4 * 4) = v;
    }
    __syncthreads();

    for (int pos = tid; pos < 68 * 32; pos += 256) {
        int r = pos >> 5, c4 = pos & 31;
        const float* row = in + r * BLUR_IN_W + c4 * 4;
        float4 a = *reinterpret_cast<const float4*>(row);
        float4 bb = *reinterpret_cast<const float4*>(row + 4);
        float4 cc = *reinterpret_cast<const float4*>(row + 8);
        float4 o;
        o.x = a.z + 4.f * a.w + 6.f * bb.x + 4.f * bb.y + bb.z;
        o.y = a.w + 4.f * bb.x + 6.f * bb.y + 4.f * bb.z + bb.w;
        o.z = bb.x + 4.f * bb.y + 6.f * bb.z + 4.f * bb.w + cc.x;
        o.w = bb.y + 4.f * bb.z + 6.f * bb.w + 4.f * cc.x + cc.y;
        *reinterpret_cast<float4*>(hb + r * 128 + c4 * 4) = o;
    }
    __syncthreads();

    float ss = 0.f;
    for (int pos = tid; pos < 64 * 32; pos += 256) {
        int r = pos >> 5, c4 = pos & 31;
        const float* col = hb + r * 128 + c4 * 4;
        float4 h0v = *reinterpret_cast<const float4*>(col);
        float4 h1v = *reinterpret_cast<const float4*>(col + 128);
        float4 h2v = *reinterpret_cast<const float4*>(col + 256);
        float4 h3v = *reinterpret_cast<const float4*>(col + 384);
        float4 h4v = *reinterpret_cast<const float4*>(col + 512);
        // v0..v3 at ix = 4*c4 + {0,1,2,3}, iy = h0 + r
        float v0 = (h0v.x + 4.f * h1v.x + 6.f * h2v.x + 4.f * h3v.x + h4v.x) * (1.f / 256.f);
        float v1 = (h0v.y + 4.f * h1v.y + 6.f * h2v.y + 4.f * h3v.y + h4v.y) * (1.f / 256.f);
        float v2 = (h0v.z + 4.f * h1v.z + 6.f * h2v.z + 4.f * h3v.z + h4v.z) * (1.f / 256.f);
        float v3 = (h0v.w + 4.f * h1v.w + 6.f * h2v.w + 4.f * h3v.w + h4v.w) * (1.f / 256.f);
        ss += v0 * v0 + v1 * v1 + v2 * v2 + v3 * v3;

        unsigned short hh[4]; unsigned short ll[4];
#pragma unroll
        for (int j = 0; j < 4; j++) {
            float v = (j == 0) ? v0 : (j == 1) ? v1 : (j == 2) ? v2 : v3;
            __nv_bfloat16 hbv = __float2bfloat16(v);
            __nv_bfloat16 lbv = __float2bfloat16(v - __bfloat162float(hbv));
            hh[j] = __bfloat16_as_ushort(hbv);
            ll[j] = __bfloat16_as_ushort(lbv);
        }

        int iy = h0 + r;
        int py = iy & 1;
        int prow = (iy >> 1) + 1;
        long rowOff = (long)prow * 64;
        long p0b = ((long)((b * 2 + py) * 3 + 0) * 256 + c) * PL_SIZE + rowOff;
        long p1b = ((long)((b * 2 + py) * 3 + 1) * 256 + c) * PL_SIZE + rowOff;
        long p2b = ((long)((b * 2 + py) * 3 + 2) * 256 + c) * PL_SIZE + rowOff;
        int col2 = 2 * c4;

        // pvar2 (px=0): even ix -> v0 at col2, v2 at col2+1 (u32 pack)
        *reinterpret_cast<unsigned*>(&g_ph[p2b + col2]) = (unsigned)hh[0] | ((unsigned)hh[2] << 16);
        *reinterpret_cast<unsigned*>(&g_pl[p2b + col2]) = (unsigned)ll[0] | ((unsigned)ll[2] << 16);
        // pvar1 (px=1, x(2c+1)): v1 (ix=4c4+1) at col2, v3 at col2+1
        *reinterpret_cast<unsigned*>(&g_ph[p1b + col2]) = (unsigned)hh[1] | ((unsigned)hh[3] << 16);
        *reinterpret_cast<unsigned*>(&g_pl[p1b + col2]) = (unsigned)ll[1] | ((unsigned)ll[3] << 16);
        // pvar0 (px=1, x(2c-1)): v1 at col2+1, v3 at col2+2 (skip if col>63)
        g_ph[p0b + col2 + 1] = __ushort_as_bfloat16(hh[1]);
        g_pl[p0b + col2 + 1] = __ushort_as_bfloat16(ll[1]);
        if (c4 < 31) {
            g_ph[p0b + col2 + 2] = __ushort_as_bfloat16(hh[3]);
            g_pl[p0b + col2 + 2] = __ushort_as_bfloat16(ll[3]);
        }
    }
#pragma unroll
    for (int o = 16; o; o >>= 1) ss += __shfl_xor_sync(0xffffffffu, ss, o);
    if ((tid & 31) == 0) red[tid >> 5] = ss;
    __syncthreads();
    if (tid == 0) {
        float t = 0.f;
#pragma unroll
        for (int k = 0; k < 8; k++) t += red[k];
        g_partial[blockIdx.x] = t;
    }
}

// ============================ K3: wsplit + rscale + alpha ============================
__global__ __launch_bounds__(256) void wsplit_kernel(const float* __restrict__ w,
                                                     const float* __restrict__ norm_g) {
    __shared__ float ws[2304];
    __shared__ float rs[256];
    __shared__ float red[8];
    const int o = blockIdx.x;
    const int b = blockIdx.y;
    const int tid = threadIdx.x;

    const float4* wsrc = reinterpret_cast<const float4*>(w + (long)o * 2304);
    for (int i = tid; i < 576; i += 256)
        *reinterpret_cast<float4*>(ws + i * 4) = wsrc[i];

    {
        int p = b * 256 + tid;
        float ssum = g_partial[2 * p] + g_partial[2 * p + 1];
        float ms = ssum * (1.f / 16384.f);
        rs[tid] = rsqrtf(ms + 1e-8f) * norm_g[tid] * g_style[p];
    }
    __syncthreads();

    {
        float sv = g_style[b * 256 + tid];
        float wq = 0.f;
#pragma unroll
        for (int t = 0; t < 9; t++) { float v = ws[tid * 9 + t]; wq += v * v; }
        float pa = sv * sv * wq;
#pragma unroll
        for (int off = 16; off; off >>= 1) pa += __shfl_xor_sync(0xffffffffu, pa, off);
        if ((tid & 31) == 0) red[tid >> 5] = pa;
    }

    {
        const float rsc = rs[tid];
        long dstBase = (long)(b * 256 + o) * 2304 + tid;
#pragma unroll
        for (int t = 0; t < 9; t++) {
            float v = ws[tid * 9 + t] * rsc;
            __nv_bfloat16 h = __float2bfloat16(v);
            g_wAb_hi[dstBase + t * 256] = h;
            g_wAb_lo[dstBase + t * 256] = __float2bfloat16(v - __bfloat162float(h));
        }
    }

    __syncthreads();
    if (tid == 0) {
        float acc = 0.f;
#pragma unroll
        for (int k = 0; k < 8; k++) acc += red[k];
        const float sc = 1.f / 48.f;  // 1/sqrt(256*9)
        g_alpha[b * 256 + o] = sc * rsqrtf(sc * sc * acc + 1e-8f);
    }
}

// ============================ K4: HMMA conv GEMM ============================
// CTA tile: M=128 (o), N=64 (one output row). grid (64,2,8).
// K = 2304 = 36 chunks of 64 (k = t*256+ic). bf16 split: C = AhiBhi+AhiBlo+AloBhi
// ALL staging (A and B, hi and lo) via cp.async.cg 16B from pre-split planes.
// smem: A hi/lo 16+16KB, B hi/lo 8+8KB, double-buffered = 96KB -> 2 CTAs/SM.

#define SA_H(st) ((st) * 16384)
#define SA_L(st) (32768 + (st) * 16384)
#define SB_H(st) (65536 + (st) * 8192)
#define SB_L(st) (81920 + (st) * 8192)
#define CONV_SMEM 98304

__global__ __launch_bounds__(256, 2)
void mma_conv_kernel(const float* __restrict__ conv_b, float* __restrict__ out) {
    extern __shared__ __align__(1024) char smem[];
    const uint32_t sb = smem_to_u32(smem);
    const int tid = threadIdx.x;
    const int lane = tid & 31;
    const int wid = tid >> 5;
    const int warpM = wid >> 1;         // 0..3 (32 rows each)
    const int warpN = wid & 1;          // 0..1 (32 cols each)
    const int b = blockIdx.z;
    const int mBase = blockIdx.y * 128;
    const int oy = blockIdx.x;          // output row
    const int nBase = blockIdx.x * 64;

    // ---- A staging: 8 lanes per row-line ----
    const int aj = tid & 7;
    const int ar0 = tid >> 3;           // 0..31

    // ---- B staging: 4 threads per ic-row, 2 units each ----
    const int icB = tid >> 2;           // 0..63
    const int u0 = (tid & 3) * 2;       // 0,2,4,6
    const int bsw0 = icB * 128 + (((u0    ) ^ (icB & 7)) & 7) * 16;
    const int bsw1 = icB * 128 + (((u0 + 1) ^ (icB & 7)) & 7) * 16;

    // ---- fragment constants ----
    const int laneRow = lane & 15;
    const int laneSel = lane >> 4;
    const int mW = warpM * 32;
    const int nW = warpN * 32;
    int mRowB[2], mRow7[2];
#pragma unroll
    for (int mt = 0; mt < 2; mt++) {
        int m = mW + mt * 16 + laneRow;
        mRowB[mt] = m * 128;
        mRow7[mt] = m & 7;
    }
    const int bKRow = laneRow * 128;
    const int bK7 = laneRow & 7;
    int bUn[2];
#pragma unroll
    for (int nt2 = 0; nt2 < 2; nt2++)
        bUn[nt2] = warpN * 4 + nt2 * 2 + laneSel;   // 0..7

    float acc[2][4][4];
#pragma unroll
    for (int i = 0; i < 2; i++)
#pragma unroll
        for (int j = 0; j < 4; j++)
#pragma unroll
            for (int k = 0; k < 4; k++) acc[i][j][k] = 0.f;

    auto issueA = [&](int stage, int chunk) {
#pragma unroll
        for (int p = 0; p < 4; p++) {
            int r = ar0 + 32 * p;
            long src = (long)(b * 256 + mBase + r) * 2304 + chunk * 64 + aj * 8;
            int sw = r * 128 + ((aj ^ (r & 7)) & 7) * 16;
            CP_ASYNC16(sb + SA_H(stage) + sw, g_wAb_hi + src);
            CP_ASYNC16(sb + SA_L(stage) + sw, g_wAb_lo + src);
        }
    };
    auto issueB = [&](int stage, int chunk) {
        int tap = chunk >> 2;
        int icq = chunk & 3;
        int ty = (tap >= 6) ? 2 : (tap >= 3 ? 1 : 0);
        int tx = tap - ty * 3;
        int py = (ty == 1) ? 0 : 1;
        int pvar = (tx == 0) ? 0 : (tx == 2 ? 1 : 2);
        int row = oy + (ty != 0);
        long base = ((long)((b * 2 + py) * 3 + pvar) * 256 + icq * 64 + icB)
                    * (long)PL_SIZE + (long)row * 64;
        CP_ASYNC16(sb + SB_H(stage) + bsw0, g_ph + base + u0 * 8);
        CP_ASYNC16(sb + SB_H(stage) + bsw1, g_ph + base + (u0 + 1) * 8);
        CP_ASYNC16(sb + SB_L(stage) + bsw0, g_pl + base + u0 * 8);
        CP_ASYNC16(sb + SB_L(stage) + bsw1, g_pl + base + (u0 + 1) * 8);
    };

    // ===== prologue: fill stage 0 =====
    issueA(0, 0);
    issueB(0, 0);
    CP_COMMIT();
    CP_WAIT_ALL();
    __syncthreads();

    // ===== mainloop =====
    for (int chunk = 0; chunk < 36; ++chunk) {
        const int cur = chunk & 1;
        const int nxt = cur ^ 1;
        const bool hasNext = (chunk + 1 < 36);
        if (hasNext) {
            issueA(nxt, chunk + 1);
            issueB(nxt, chunk + 1);
            CP_COMMIT();
        }

        const uint32_t aH_base = sb + SA_H(cur);
        const uint32_t aL_base = sb + SA_L(cur);
        const uint32_t bH_base = sb + SB_H(cur);
        const uint32_t bL_base = sb + SB_L(cur);

#pragma unroll
        for (int kk = 0; kk < 4; kk++) {
            uint32_t aH[2][4], aL[2][4], bH[2][4], bL[2][4];
#pragma unroll
            for (int mt = 0; mt < 2; mt++) {
                int u = kk * 2 + laneSel;
                int off = mRowB[mt] + ((u ^ mRow7[mt]) & 7) * 16;
                ldmat_x4(aH[mt], aH_base + off);
                ldmat_x4(aL[mt], aL_base + off);
            }
#pragma unroll
            for (int nt2 = 0; nt2 < 2; nt2++) {
                int off = kk * 16 * 128 + bKRow + ((bUn[nt2] ^ bK7) & 7) * 16;
                ldmat_x4_t(bH[nt2], bH_base + off);
                ldmat_x4_t(bL[nt2], bL_base + off);
            }
#pragma unroll
            for (int mt = 0; mt < 2; mt++) {
#pragma unroll
                for (int nt = 0; nt < 4; nt++) {
                    int nt2 = nt >> 1, sub = (nt & 1) * 2;
                    mma16816(acc[mt][nt], aH[mt], bH[nt2][sub], bH[nt2][sub + 1]);
                    mma16816(acc[mt][nt], aH[mt], bL[nt2][sub], bL[nt2][sub + 1]);
                    mma16816(acc[mt][nt], aL[mt], bH[nt2][sub], bH[nt2][sub + 1]);
                }
            }
        }

        CP_WAIT_ALL();
        __syncthreads();
    }

    // ===== epilogue: alpha, bias, scaled LeakyReLU =====
    const int rowInTile = lane >> 2;
    const int colInTile = (lane & 3) * 2;
#pragma unroll
    for (int mt = 0; mt < 2; mt++) {
        int o0 = mBase + mW + mt * 16 + rowInTile;
        int o1 = o0 + 8;
        float al0 = g_alpha[b * 256 + o0], bi0 = conv_b[o0];
        float al1 = g_alpha[b * 256 + o1], bi1 = conv_b[o1];
        float* p0 = out + (long)(b * 256 + o0) * 4096 + nBase + nW + colInTile;
        float* p1 = out + (long)(b * 256 + o1) * 4096 + nBase + nW + colInTile;
#pragma unroll
        for (int nt = 0; nt < 4; nt++) {
            float2 v0, v1;
            float v;
            v = acc[mt][nt][0] * al0 + bi0;
            v0.x = (v >= 0.f ? v : LRELU_SLOPE * v) * SQRT2F;
            v = acc[mt][nt][1] * al0 + bi0;
            v0.y = (v >= 0.f ? v : LRELU_SLOPE * v) * SQRT2F;
            v = acc[mt][nt][2] * al1 + bi1;
            v1.x = (v >= 0.f ? v : LRELU_SLOPE * v) * SQRT2F;
            v = acc[mt][nt][3] * al1 + bi1;
            v1.y = (v >= 0.f ? v : LRELU_SLOPE * v) * SQRT2F;
            *reinterpret_cast<float2*>(p0 + nt * 8) = v0;
            *reinterpret_cast<float2*>(p1 + nt * 8) = v1;
        }
    }
}

// ============================ launch ============================
extern "C" void kernel_launch(void* const* d_in, const int* in_sizes, int n_in,
                              void* d_out, int out_size) {
    const float* x       = (const float*)d_in[0];  // [8,256,128,128]
    const float* s       = (const float*)d_in[1];  // [8,512]
    const float* conv_w  = (const float*)d_in[2];  // [256,256,3,3]
    const float* conv_b  = (const float*)d_in[3];  // [256]
    const float* style_w = (const float*)d_in[4];  // [256,512]
    const float* style_b = (const float*)d_in[5];  // [256]
    const float* norm_g  = (const float*)d_in[6];  // [256]
    float* out = (float*)d_out;                    // [8,256,64,64]

    static int attr_set = 0;
    if (!attr_set) {
        cudaFuncSetAttribute(mma_conv_kernel,
                             cudaFuncAttributeMaxDynamicSharedMemorySize, CONV_SMEM);
        cudaFuncSetAttribute(blur_kernel,
                             cudaFuncAttributeMaxDynamicSharedMemorySize, BLUR_SMEM);
        attr_set = 1;
    }

    style_kernel<<<256, 256>>>(s, style_w, style_b);                    // launch 1
    blur_kernel<<<4224, 256, BLUR_SMEM>>>(x);                          // launch 2
    wsplit_kernel<<<dim3(256, 8), 256>>>(conv_w, norm_g);              // launch 3
    mma_conv_kernel<<<dim3(64, 2, 8), 256, CONV_SMEM>>>(conv_b, out);  // launch 4
}